// round 14
// baseline (speedup 1.0000x reference)
#include <cuda_runtime.h>
#include <cuda_fp16.h>
#include <cstdint>

// ===================== problem constants =====================
static constexpr int NMAXC = 100000;
static constexpr int EMAXC = 1600000;
#define EPSV 1e-5f

// ===================== device scratch (static, no allocs) =====================
__device__ int   g_isI64;
__device__ int   g_deg[NMAXC];
__device__ float g_dinv[NMAXC];
__device__ int   g_colptr[NMAXC + 1];
__device__ int   g_cursor[NMAXC];
__device__ int   g_blk[512];
__device__ __align__(8) int2 g_edge[EMAXC];   // (srcrow, weight-bits)

__device__ __align__(16) __half g_tc[(size_t)NMAXC * 256];   // interleaved hop1pre|hop2pre
__device__ __align__(16) __half g_t1h[(size_t)NMAXC * 128];  // x-fp16 / hop2 intermediate
__device__ __align__(16) __half g_hA[(size_t)NMAXC * 384];   // fp16 activations
__device__ __align__(16) __half g_hB[(size_t)NMAXC * 384];
__device__ float g_bnsum[384];
__device__ float g_bnsq[384];
__device__ float g_bnsc[384];
__device__ float g_bnsh[384];

// transposed fp16-split weights: [NOUT, K] row-major, hi & lo
static constexpr int BW_TOT = 384*128 + 384*384 + 192*384 + 64*192;
__device__ __align__(16) __half g_Bhi[BW_TOT];
__device__ __align__(16) __half g_Blo[BW_TOT];
static constexpr int BOFF0 = 0;
static constexpr int BOFF1 = 384*128;
static constexpr int BOFF2 = BOFF1 + 384*384;
static constexpr int BOFFF = BOFF2 + 192*384;

// ===================== side stream for graph-captured fork/join =====================
namespace {
struct StreamInit {
    cudaStream_t s1 = nullptr;
    cudaEvent_t  ev[6] = {};
    bool ok = false;
    StreamInit() {
        ok = (cudaStreamCreateWithFlags(&s1, cudaStreamNonBlocking) == cudaSuccess);
        for (int i = 0; i < 6 && ok; i++)
            ok = (cudaEventCreateWithFlags(&ev[i], cudaEventDisableTiming) == cudaSuccess);
    }
};
StreamInit g_si;
}

// ===================== helpers =====================
__device__ __forceinline__ uint32_t smem_u32(const void* p) {
    uint32_t a;
    asm("{ .reg .u64 t; cvta.to.shared.u64 t, %1; cvt.u32.u64 %0, t; }" : "=r"(a) : "l"(p));
    return a;
}

// ===================== edge-index format detection =====================
__global__ void k_detect(const int* __restrict__ ei32, int nwords) {
    __shared__ int anyNonZero;
    if (threadIdx.x == 0) anyNonZero = 0;
    __syncthreads();
    int lim = min(nwords, 4096);
    for (int i = 1 + 2 * threadIdx.x; i < lim; i += 2 * blockDim.x)
        if (ei32[i] != 0) anyNonZero = 1;
    __syncthreads();
    if (threadIdx.x == 0) g_isI64 = (anyNonZero == 0) ? 1 : 0;
}
__device__ __forceinline__ int load_idx(const void* ei, long long pos) {
    if (g_isI64) return (int)((const long long*)ei)[pos];
    return ((const int*)ei)[pos];
}

// ===================== graph preprocessing =====================
__global__ void k_deg(const void* __restrict__ ei, int E, int n) {
    int e = blockIdx.x * blockDim.x + threadIdx.x;
    if (e < E) {
        int c = load_idx(ei, (long long)E + e);
        if ((unsigned)c < (unsigned)n) atomicAdd(&g_deg[c], 1);
    }
}
__global__ void k_blksum(int n) {
    __shared__ int sh[256];
    int i = blockIdx.x * 256 + threadIdx.x;
    int v = (i < n) ? g_deg[i] : 0;
    if (i < n) g_dinv[i] = (v > 0) ? rsqrtf((float)v) : 0.f;
    sh[threadIdx.x] = v;
    __syncthreads();
    for (int o = 128; o > 0; o >>= 1) {
        if (threadIdx.x < o) sh[threadIdx.x] += sh[threadIdx.x + o];
        __syncthreads();
    }
    if (threadIdx.x == 0) g_blk[blockIdx.x] = sh[0];
}
__global__ void k_scanblk(int nblk) {
    __shared__ int sh[512];
    int t = threadIdx.x;
    int v = (t < nblk) ? g_blk[t] : 0;
    sh[t] = v;
    __syncthreads();
    for (int o = 1; o < 512; o <<= 1) {
        int x = (t >= o) ? sh[t - o] : 0;
        __syncthreads();
        sh[t] += x;
        __syncthreads();
    }
    if (t < nblk) g_blk[t] = sh[t] - v;
}
__global__ void k_scanout(int n) {
    __shared__ int sh[256];
    int t = threadIdx.x;
    int i = blockIdx.x * 256 + t;
    int v = (i < n) ? g_deg[i] : 0;
    sh[t] = v;
    __syncthreads();
    for (int o = 1; o < 256; o <<= 1) {
        int x = (t >= o) ? sh[t - o] : 0;
        __syncthreads();
        sh[t] += x;
        __syncthreads();
    }
    int excl = g_blk[blockIdx.x] + sh[t] - v;
    if (i < n) g_colptr[i] = excl;
    if (i == n - 1) g_colptr[n] = excl + v;
}
__global__ void k_scatter(const void* __restrict__ ei, int E, int n) {
    int e = blockIdx.x * blockDim.x + threadIdx.x;
    if (e < E) {
        int r = load_idx(ei, e);
        int c = load_idx(ei, (long long)E + e);
        if ((unsigned)r >= (unsigned)n || (unsigned)c >= (unsigned)n) return;
        float w = g_dinv[r] * g_dinv[c];
        int p = g_colptr[c] + atomicAdd(&g_cursor[c], 1);
        g_edge[p] = make_int2(r, __float_as_int(w));
    }
}

// ===================== x fp32 -> fp16 conversion =====================
__global__ void k_cvtx(const float* __restrict__ x, __half* __restrict__ xh, int total8) {
    int idx = blockIdx.x * blockDim.x + threadIdx.x;
    if (idx >= total8) return;
    const float4* src = (const float4*)x + 2 * idx;
    float4 v0 = src[0], v1 = src[1];
    union { __half2 h[4]; uint4 u; } pk;
    pk.h[0] = __floats2half2_rn(v0.x, v0.y);
    pk.h[1] = __floats2half2_rn(v0.z, v0.w);
    pk.h[2] = __floats2half2_rn(v1.x, v1.y);
    pk.h[3] = __floats2half2_rn(v1.z, v1.w);
    ((uint4*)xh)[idx] = pk.u;
}

// ===================== weight prep: transpose + fp16 hi/lo split =====================
__global__ void k_prepB(const float* __restrict__ W, int K, int Nj, int nstack, int off) {
    int idx = blockIdx.x * blockDim.x + threadIdx.x;
    int total = nstack * K * Nj;
    if (idx >= total) return;
    int n = idx % Nj;
    int k = (idx / Nj) % K;
    int s = idx / (Nj * K);
    float v = W[idx];
    __half h = __float2half_rn(v);
    __half l = __float2half_rn(v - __half2float(h));
    int o = off + ((s * Nj + n) * K + k);
    g_Bhi[o] = h;
    g_Blo[o] = l;
}

// ===================== fp16 HMMA GEMM (8 warps, 64x32 warp tiles, fused hi/lo B x4) =====================
template <int KTOT, int NOUT, int BN, bool FUSE, bool OUT32>
__global__ __launch_bounds__(256, 2)
void k_hgemm(const __half* __restrict__ A,
             const __half* __restrict__ Bhi,
             const __half* __restrict__ Blo,
             const float* __restrict__ bias,
             void* __restrict__ d0, int s0,
             void* __restrict__ d1, int s1,
             void* __restrict__ d2, int s2,
             int nrows)
{
    static_assert(BN == 128 || BN == 64, "");
    constexpr int NC  = KTOT / 32;
    constexpr int STR = 40;
    constexpr int WN  = (BN == 128) ? 4 : 2;
    constexpr int WTM = (BN == 128) ? 64 : 32;
    constexpr int MT  = WTM / 16;
    constexpr int NT  = 4;
    constexpr int A_BYTES = 128 * STR * 2;
    constexpr int B_BYTES = BN * STR * 2;
    constexpr int STAGE = A_BYTES + 2 * B_BYTES;
    constexpr int BPT = BN * 8 / 256;

    extern __shared__ __align__(16) char sm[];

    const int tid  = threadIdx.x;
    const int lane = tid & 31;
    const int w    = tid >> 5;
    const int warp_m = w / WN;
    const int warp_n = w % WN;
    const int rowBase = blockIdx.y * 128;
    const int colBase = blockIdx.x * BN;

    const int arow = tid >> 1;
    const int acb  = tid & 1;
    const int agrow = min(rowBase + arow, nrows - 1);

    uint4 pah[2];

    auto load_A = [&](int c) {
        const uint4* src = (const uint4*)(A + (size_t)agrow * KTOT + c * 32 + acb * 16);
        pah[0] = src[0];
        pah[1] = src[1];
    };
    auto cpasync_B = [&](int c, int s) {
        char* base = sm + s * STAGE + A_BYTES;
#pragma unroll
        for (int j = 0; j < BPT; j++) {
            int idx  = tid + j * 256;
            int arr  = idx / (BN * 4);
            int cidx = idx % (BN * 4);
            int brow = cidx >> 2, bq = cidx & 3;
            const __half* gp = (arr ? Blo : Bhi) +
                               (size_t)(colBase + brow) * KTOT + c * 32 + bq * 8;
            uint32_t sa = smem_u32(base + arr * B_BYTES + brow * 80 + bq * 16);
            asm volatile("cp.async.cg.shared.global [%0], [%1], 16;" :: "r"(sa), "l"(gp));
        }
        asm volatile("cp.async.commit_group;" ::: "memory");
    };
    auto store_A = [&](int c, int s) {
        uint16_t* sA = (uint16_t*)(sm + s * STAGE);
        uint32_t aoff = arow * STR + acb * 16;
        if constexpr (FUSE) {
#pragma unroll
            for (int i = 0; i < 2; i++) {
                uint4 u = pah[i];
                uint32_t* uu = (uint32_t*)&u;
                uint4 o;
                uint32_t* oo = (uint32_t*)&o;
#pragma unroll
                for (int j = 0; j < 4; j++) {
                    int kb = c * 32 + acb * 16 + i * 8 + j * 2;
                    float2 f = __half22float2(*(__half2*)&uu[j]);
                    f.x = fmaxf(fmaf(f.x, g_bnsc[kb + 0], g_bnsh[kb + 0]), 0.f);
                    f.y = fmaxf(fmaf(f.y, g_bnsc[kb + 1], g_bnsh[kb + 1]), 0.f);
                    __half2 h = __floats2half2_rn(f.x, f.y);
                    oo[j] = *(uint32_t*)&h;
                }
                *(uint4*)&sA[aoff + i * 8] = o;
            }
        } else {
            *(uint4*)&sA[aoff]     = pah[0];
            *(uint4*)&sA[aoff + 8] = pah[1];
        }
    };

    float acc[MT][NT][4];
#pragma unroll
    for (int mt = 0; mt < MT; mt++)
#pragma unroll
        for (int nt = 0; nt < NT; nt++)
#pragma unroll
            for (int i = 0; i < 4; i++) acc[mt][nt][i] = 0.f;

    const int arow_lm = warp_m * WTM + (lane & 7) + ((lane >> 3) & 1) * 8;
    const int acol_lm = (lane >> 4) * 8;
    const int brow_lm = warp_n * 32 + (lane & 7);
    const int bcol_lm = ((lane >> 3) & 1) * 8;
    const uint32_t bsel = (lane & 16) ? (uint32_t)(BN * STR) : 0u;

    auto compute = [&](int s) {
        const uint16_t* sA = (const uint16_t*)(sm + s * STAGE);
        const uint16_t* sB = (const uint16_t*)(sm + s * STAGE + A_BYTES) + bsel;
#pragma unroll
        for (int ks = 0; ks < 2; ks++) {
            uint32_t ah[MT][4], bf[NT][4];
#pragma unroll
            for (int mt = 0; mt < MT; mt++) {
                uint32_t addr = smem_u32(&sA[(arow_lm + mt * 16) * STR + acol_lm + ks * 16]);
                asm volatile("ldmatrix.sync.aligned.m8n8.x4.shared.b16 {%0,%1,%2,%3}, [%4];"
                    : "=r"(ah[mt][0]), "=r"(ah[mt][1]), "=r"(ah[mt][2]), "=r"(ah[mt][3]) : "r"(addr));
            }
#pragma unroll
            for (int nt = 0; nt < NT; nt++) {
                uint32_t addr = smem_u32(&sB[(brow_lm + nt * 8) * STR + bcol_lm + ks * 16]);
                asm volatile("ldmatrix.sync.aligned.m8n8.x4.shared.b16 {%0,%1,%2,%3}, [%4];"
                    : "=r"(bf[nt][0]), "=r"(bf[nt][1]), "=r"(bf[nt][2]), "=r"(bf[nt][3]) : "r"(addr));
            }
#pragma unroll
            for (int mt = 0; mt < MT; mt++)
#pragma unroll
                for (int nt = 0; nt < NT; nt++) {
                    asm volatile(
                        "mma.sync.aligned.m16n8k16.row.col.f32.f16.f16.f32 "
                        "{%0,%1,%2,%3}, {%4,%5,%6,%7}, {%8,%9}, {%0,%1,%2,%3};"
                        : "+f"(acc[mt][nt][0]), "+f"(acc[mt][nt][1]),
                          "+f"(acc[mt][nt][2]), "+f"(acc[mt][nt][3])
                        : "r"(ah[mt][0]), "r"(ah[mt][1]), "r"(ah[mt][2]), "r"(ah[mt][3]),
                          "r"(bf[nt][0]), "r"(bf[nt][1]));
                    asm volatile(
                        "mma.sync.aligned.m16n8k16.row.col.f32.f16.f16.f32 "
                        "{%0,%1,%2,%3}, {%4,%5,%6,%7}, {%8,%9}, {%0,%1,%2,%3};"
                        : "+f"(acc[mt][nt][0]), "+f"(acc[mt][nt][1]),
                          "+f"(acc[mt][nt][2]), "+f"(acc[mt][nt][3])
                        : "r"(ah[mt][0]), "r"(ah[mt][1]), "r"(ah[mt][2]), "r"(ah[mt][3]),
                          "r"(bf[nt][2]), "r"(bf[nt][3]));
                }
        }
    };

    // ---- pipeline ----
    cpasync_B(0, 0);
    load_A(0);
    store_A(0, 0);
    asm volatile("cp.async.wait_group 0;" ::: "memory");
    __syncthreads();
    for (int c = 0; c < NC; c++) {
        if (c + 1 < NC) {
            cpasync_B(c + 1, (c + 1) & 1);
            load_A(c + 1);
        }
        compute(c & 1);
        if (c + 1 < NC) {
            store_A(c + 1, (c + 1) & 1);
            asm volatile("cp.async.wait_group 0;" ::: "memory");
        }
        __syncthreads();
    }

    // ---- epilogue ----
    const int g = blockIdx.x;
#pragma unroll
    for (int nt = 0; nt < NT; nt++) {
        int ccol = warp_n * 32 + nt * 8 + (lane & 3) * 2;
        int gcol = colBase + ccol;
        float bx = bias[gcol], by = bias[gcol + 1];
#pragma unroll
        for (int mt = 0; mt < MT; mt++) {
            int r0 = rowBase + warp_m * WTM + mt * 16 + (lane >> 2);
            int r1 = r0 + 8;
            float v00 = acc[mt][nt][0] + bx, v01 = acc[mt][nt][1] + by;
            float v10 = acc[mt][nt][2] + bx, v11 = acc[mt][nt][3] + by;
            if (OUT32 && g == 0) {
                float* dp = (float*)d0;
                if (r0 < nrows) *(float2*)(dp + (size_t)r0 * s0 + ccol) = make_float2(v00, v01);
                if (r1 < nrows) *(float2*)(dp + (size_t)r1 * s0 + ccol) = make_float2(v10, v11);
            } else {
                __half* dp = (__half*)((g == 0) ? d0 : ((g == 1) ? d1 : d2));
                int st = (g == 0) ? s0 : ((g == 1) ? s1 : s2);
                if (r0 < nrows) *(__half2*)(dp + (size_t)r0 * st + ccol) = __floats2half2_rn(v00, v01);
                if (r1 < nrows) *(__half2*)(dp + (size_t)r1 * st + ccol) = __floats2half2_rn(v10, v11);
            }
        }
    }
}

template <int KTOT, int NOUT, int BN, bool FUSE, bool OUT32>
static void launch_hgemm(const __half* A, const __half* bhi, const __half* blo,
                         const float* bias, void* d0, int s0, void* d1, int s1,
                         void* d2, int s2, int nrows) {
    constexpr int STAGE = (128 * 40 * 2) + 2 * (BN * 40 * 2);
    int smem = 2 * STAGE;
    cudaFuncSetAttribute(k_hgemm<KTOT, NOUT, BN, FUSE, OUT32>,
                         cudaFuncAttributeMaxDynamicSharedMemorySize, smem);
    k_hgemm<KTOT, NOUT, BN, FUSE, OUT32><<<dim3(NOUT / BN, (nrows + 127) / 128), 256, smem>>>(
        A, bhi, blo, bias, d0, s0, d1, s1, d2, s2, nrows);
}

// ===================== fused first-hop SpMM (fp16 gather, dual fp16 output) =====================
template <int CW>
__global__ __launch_bounds__(256)
void k_spmm1(const __half* __restrict__ src,
             __half* __restrict__ outA, int sA,
             __half* __restrict__ outB, int n)
{
    constexpr int VL = CW / 32;
    int node = blockIdx.x * 8 + (threadIdx.x >> 5);
    if (node >= n) return;
    int lane = threadIdx.x & 31;
    int s = g_colptr[node];
    int e = g_colptr[node + 1];
    float acc[VL];
#pragma unroll
    for (int i = 0; i < VL; i++) acc[i] = 0.f;

    for (int p = s; p < e; p++) {
        int2  ed = g_edge[p];
        int   r = ed.x;
        float w = __int_as_float(ed.y);
        const __half* hp = src + (size_t)r * CW + lane * VL;
        if constexpr (VL == 8) {
            uint4 u = *(const uint4*)hp;
            const __half2* h2 = (const __half2*)&u;
#pragma unroll
            for (int i = 0; i < 4; i++) {
                float2 f = __half22float2(h2[i]);
                acc[2 * i]     = fmaf(w, f.x, acc[2 * i]);
                acc[2 * i + 1] = fmaf(w, f.y, acc[2 * i + 1]);
            }
        } else {
            uint2 u = *(const uint2*)hp;
            const __half2* h2 = (const __half2*)&u;
#pragma unroll
            for (int i = 0; i < 2; i++) {
                float2 f = __half22float2(h2[i]);
                acc[2 * i]     = fmaf(w, f.x, acc[2 * i]);
                acc[2 * i + 1] = fmaf(w, f.y, acc[2 * i + 1]);
            }
        }
    }
    __half2 hh[VL / 2];
#pragma unroll
    for (int i = 0; i < VL / 2; i++) hh[i] = __floats2half2_rn(acc[2 * i], acc[2 * i + 1]);
    __half* o = (lane < 16) ? (outA + (size_t)node * sA + lane * VL)
                            : (outB + (size_t)node * (CW / 2) + (lane - 16) * VL);
    if constexpr (VL == 8) *(uint4*)o = *(uint4*)hh;
    else                   *(uint2*)o = *(uint2*)hh;
}

// second-hop SpMM: fp16 gather -> fp16 out
template <int CW>
__global__ __launch_bounds__(256)
void k_spmm2(const __half* __restrict__ src, __half* __restrict__ out, int sO, int n)
{
    constexpr int VL = CW / 32;
    int node = blockIdx.x * 8 + (threadIdx.x >> 5);
    if (node >= n) return;
    int lane = threadIdx.x & 31;
    int s = g_colptr[node];
    int e = g_colptr[node + 1];
    float acc[VL];
#pragma unroll
    for (int i = 0; i < VL; i++) acc[i] = 0.f;

    for (int p = s; p < e; p++) {
        int2  ed = g_edge[p];
        int   r = ed.x;
        float w = __int_as_float(ed.y);
        const __half* hp = src + (size_t)r * CW + lane * VL;
        if constexpr (VL == 4) {
            uint2 u = *(const uint2*)hp;
            const __half2* h2 = (const __half2*)&u;
#pragma unroll
            for (int i = 0; i < 2; i++) {
                float2 f = __half22float2(h2[i]);
                acc[2 * i]     = fmaf(w, f.x, acc[2 * i]);
                acc[2 * i + 1] = fmaf(w, f.y, acc[2 * i + 1]);
            }
        } else {
            uint u = *(const uint*)hp;
            float2 f = __half22float2(*(const __half2*)&u);
            acc[0] = fmaf(w, f.x, acc[0]);
            acc[1] = fmaf(w, f.y, acc[1]);
        }
    }
    __half* o = out + (size_t)node * sO + lane * VL;
    __half2 hh[VL / 2];
#pragma unroll
    for (int i = 0; i < VL / 2; i++) hh[i] = __floats2half2_rn(acc[2 * i], acc[2 * i + 1]);
    if constexpr (VL == 4) *(uint2*)o = *(uint2*)hh;
    else                   *(uint*)o = *(uint*)hh;
}

// ===================== BatchNorm stats (128-col slice) + finalize =====================
__global__ void k_bnstats(const __half* __restrict__ H, int N, int C, int colOff) {
    int col = colOff + threadIdx.x;      // blockDim.x == 128
    int r0 = blockIdx.x * 256;
    int r1 = min(r0 + 256, N);
    float s = 0.f, s2 = 0.f;
    for (int r = r0; r < r1; r++) {
        float v = __half2float(H[(size_t)r * C + col]);
        s += v;
        s2 += v * v;
    }
    atomicAdd(&g_bnsum[col], s);
    atomicAdd(&g_bnsq[col],  s2);
}
__global__ void k_bnfin(const float* __restrict__ gma, const float* __restrict__ bet,
                        float invN) {
    int c = threadIdx.x;
    float mu  = g_bnsum[c] * invN;
    float var = g_bnsq[c] * invN - mu * mu;
    float sc  = gma[c] * rsqrtf(var + EPSV);
    g_bnsc[c] = sc;
    g_bnsh[c] = bet[c] - mu * sc;
}

extern "C" void kernel_launch(void* const* d_in, const int* in_sizes, int n_in,
                              void* d_out, int out_size) {
    const float* x    = (const float*)d_in[0];
    const void*  ei   = d_in[1];
    const float* W0   = (const float*)d_in[2];
    const float* b0   = (const float*)d_in[3];
    const float* W1   = (const float*)d_in[4];
    const float* b1   = (const float*)d_in[5];
    const float* W2   = (const float*)d_in[6];
    const float* b2   = (const float*)d_in[7];
    const float* bn0g = (const float*)d_in[8];
    const float* bn0b = (const float*)d_in[9];
    const float* bn1g = (const float*)d_in[10];
    const float* bn1b = (const float*)d_in[11];
    const float* fpW  = (const float*)d_in[12];
    const float* fpb  = (const float*)d_in[13];
    float*       out  = (float*)d_out;

    const int N = in_sizes[0] / 128;
    int E = in_sizes[1] / 2;
    if (E > EMAXC) E = in_sizes[1] / 4;

    int   *deg, *cursor;
    float *bnsum, *bnsq;
    __half *tc, *t1h, *hA, *hB, *bhi, *blo;
    cudaGetSymbolAddress((void**)&deg,    g_deg);
    cudaGetSymbolAddress((void**)&cursor, g_cursor);
    cudaGetSymbolAddress((void**)&tc,     g_tc);
    cudaGetSymbolAddress((void**)&t1h,    g_t1h);
    cudaGetSymbolAddress((void**)&hA,     g_hA);
    cudaGetSymbolAddress((void**)&hB,     g_hB);
    cudaGetSymbolAddress((void**)&bnsum,  g_bnsum);
    cudaGetSymbolAddress((void**)&bnsq,   g_bnsq);
    cudaGetSymbolAddress((void**)&bhi,    g_Bhi);
    cudaGetSymbolAddress((void**)&blo,    g_Blo);

    const float invN = 1.f / (float)N;
    const int nblk = (N + 255) / 256;
    const int sb = (N + 7) / 8;

    const bool fork = g_si.ok;
    cudaStream_t sp = fork ? g_si.s1 : (cudaStream_t)0;
    auto forkTo = [&](cudaEvent_t ev) {
        if (fork) { cudaEventRecord(ev, 0); cudaStreamWaitEvent(sp, ev, 0); }
    };
    auto joinFrom = [&](cudaEvent_t ev) {
        if (fork) { cudaEventRecord(ev, sp); cudaStreamWaitEvent(0, ev, 0); }
    };

    // -------- main: minimal critical path to layer-0 GEMM --------
    k_cvtx<<<(N * 128 / 8 + 255) / 256, 256>>>(x, t1h, N * 128 / 8);
    k_prepB<<<(3 * 128 * 128 + 255) / 256, 256>>>(W0, 128, 128, 3, BOFF0);

    // -------- fork: preproc + remaining weight prep on side stream --------
    forkTo(g_si.ev[0]);
    k_detect<<<1, 256, 0, sp>>>((const int*)ei, in_sizes[1]);
    cudaMemsetAsync(deg,    0, (size_t)N * sizeof(int), sp);
    cudaMemsetAsync(cursor, 0, (size_t)N * sizeof(int), sp);
    k_deg<<<(E + 255) / 256, 256, 0, sp>>>(ei, E, N);
    k_blksum<<<nblk, 256, 0, sp>>>(N);
    k_scanblk<<<1, 512, 0, sp>>>(nblk);
    k_scanout<<<nblk, 256, 0, sp>>>(N);
    k_scatter<<<(E + 255) / 256, 256, 0, sp>>>(ei, E, N);
    k_prepB<<<(3 * 384 * 128 + 255) / 256, 256, 0, sp>>>(W1, 384, 128, 3, BOFF1);
    k_prepB<<<(3 * 384 * 64  + 255) / 256, 256, 0, sp>>>(W2, 384,  64, 3, BOFF2);
    k_prepB<<<(192 * 64      + 255) / 256, 256, 0, sp>>>(fpW, 192, 64, 1, BOFFF);

    // -------- main: layer-0 GEMM (reads fp16 x), then BN resets --------
    launch_hgemm<128, 384, 128, false, false>(t1h, bhi + BOFF0, blo + BOFF0, b0,
                                              hA, 384, tc, 256, tc + 128, 256, N);
    cudaMemsetAsync(bnsum, 0, 384 * sizeof(float));
    cudaMemsetAsync(bnsq,  0, 384 * sizeof(float));

    // join preproc (spmm needs CSC); fork bnstats(hop0) to side
    joinFrom(g_si.ev[1]);
    forkTo(g_si.ev[2]);
    k_bnstats<<<nblk, 128, 0, sp>>>(hA, N, 384, 0);

    k_spmm1<256><<<sb, 256>>>(tc, hA + 128, 384, t1h, N);
    forkTo(g_si.ev[3]);
    k_bnstats<<<nblk, 128, 0, sp>>>(hA, N, 384, 128);
    k_spmm2<128><<<sb, 256>>>(t1h, hA + 256, 384, N);
    k_bnstats<<<nblk, 128>>>(hA, N, 384, 256);
    joinFrom(g_si.ev[4]);
    k_bnfin<<<1, 384>>>(bn0g, bn0b, invN);
    cudaMemsetAsync(bnsum, 0, 384 * sizeof(float));
    cudaMemsetAsync(bnsq,  0, 384 * sizeof(float));

    // -------- layer 1 (BN0+ReLU fused into A-load) --------
    launch_hgemm<384, 384, 128, true, false>(hA, bhi + BOFF1, blo + BOFF1, b1,
                                             hB, 384, tc, 256, tc + 128, 256, N);
    forkTo(g_si.ev[5]);
    k_bnstats<<<nblk, 128, 0, sp>>>(hB, N, 384, 0);
    k_spmm1<256><<<sb, 256>>>(tc, hB + 128, 384, t1h, N);
    forkTo(g_si.ev[0]);
    k_bnstats<<<nblk, 128, 0, sp>>>(hB, N, 384, 128);
    k_spmm2<128><<<sb, 256>>>(t1h, hB + 256, 384, N);
    k_bnstats<<<nblk, 128>>>(hB, N, 384, 256);
    joinFrom(g_si.ev[1]);
    k_bnfin<<<1, 384>>>(bn1g, bn1b, invN);

    // -------- layer 2 (BN1+ReLU fused), NOUT=192, hop width 64 --------
    __half* h2 = hA;
    launch_hgemm<384, 192, 64, true, false>(hB, bhi + BOFF2, blo + BOFF2, b2,
                                            h2, 192, tc, 128, tc + 64, 128, N);
    k_spmm1<128><<<sb, 256>>>(tc, h2 + 64, 192, t1h, N);
    k_spmm2<64><<<sb, 256>>>(t1h, h2 + 128, 192, N);

    // -------- final projection: fp32 output --------
    launch_hgemm<192, 64, 64, false, true>(h2, bhi + BOFFF, blo + BOFFF, fpb,
                                           out, 64, out, 64, out, 64, N);
}

// round 15
// speedup vs baseline: 1.0120x; 1.0120x over previous
#include <cuda_runtime.h>
#include <cuda_fp16.h>
#include <cstdint>

// ===================== problem constants =====================
static constexpr int NMAXC = 100000;
static constexpr int EMAXC = 1600000;
#define EPSV 1e-5f

// ===================== device scratch (static, no allocs) =====================
__device__ int   g_isI64;
__device__ int   g_deg[NMAXC];
__device__ float g_dinv[NMAXC];
__device__ int   g_colptr[NMAXC + 1];
__device__ int   g_cursor[NMAXC];
__device__ int   g_blk[512];
__device__ __align__(8) int2 g_edge[EMAXC];   // (srcrow, weight-bits)

__device__ __align__(16) __half g_tc[(size_t)NMAXC * 256];   // interleaved hop1pre|hop2pre
__device__ __align__(16) __half g_t1h[(size_t)NMAXC * 128];  // x-fp16 / hop2 intermediate
__device__ __align__(16) __half g_hA[(size_t)NMAXC * 384];   // fp16 activations
__device__ __align__(16) __half g_hB[(size_t)NMAXC * 384];
__device__ float g_bnsum[384];
__device__ float g_bnsq[384];
__device__ float g_bnsc[384];
__device__ float g_bnsh[384];
__device__ float g_b2f[192];                  // fused layer2+proj biases

// transposed fp16-split weights: [NOUT, K] row-major, hi & lo
static constexpr int BW_TOT = 384*128 + 384*384 + 192*384 + 64*192;
__device__ __align__(16) __half g_Bhi[BW_TOT];
__device__ __align__(16) __half g_Blo[BW_TOT];
static constexpr int BOFF0 = 0;
static constexpr int BOFF1 = 384*128;
static constexpr int BOFF2 = BOFF1 + 384*384;   // fused U = W2@fpW, [192, 384]

// ===================== side stream for graph-captured fork/join =====================
namespace {
struct StreamInit {
    cudaStream_t s1 = nullptr;
    cudaEvent_t  ev[6] = {};
    bool ok = false;
    StreamInit() {
        ok = (cudaStreamCreateWithFlags(&s1, cudaStreamNonBlocking) == cudaSuccess);
        for (int i = 0; i < 6 && ok; i++)
            ok = (cudaEventCreateWithFlags(&ev[i], cudaEventDisableTiming) == cudaSuccess);
    }
};
StreamInit g_si;
}

// ===================== helpers =====================
__device__ __forceinline__ uint32_t smem_u32(const void* p) {
    uint32_t a;
    asm("{ .reg .u64 t; cvta.to.shared.u64 t, %1; cvt.u32.u64 %0, t; }" : "=r"(a) : "l"(p));
    return a;
}

// ===================== edge-index format detection =====================
__global__ void k_detect(const int* __restrict__ ei32, int nwords) {
    __shared__ int anyNonZero;
    if (threadIdx.x == 0) anyNonZero = 0;
    __syncthreads();
    int lim = min(nwords, 4096);
    for (int i = 1 + 2 * threadIdx.x; i < lim; i += 2 * blockDim.x)
        if (ei32[i] != 0) anyNonZero = 1;
    __syncthreads();
    if (threadIdx.x == 0) g_isI64 = (anyNonZero == 0) ? 1 : 0;
}
__device__ __forceinline__ int load_idx(const void* ei, long long pos) {
    if (g_isI64) return (int)((const long long*)ei)[pos];
    return ((const int*)ei)[pos];
}

// ===================== graph preprocessing =====================
__global__ void k_deg(const void* __restrict__ ei, int E, int n) {
    int e = blockIdx.x * blockDim.x + threadIdx.x;
    if (e < E) {
        int c = load_idx(ei, (long long)E + e);
        if ((unsigned)c < (unsigned)n) atomicAdd(&g_deg[c], 1);
    }
}
__global__ void k_blksum(int n) {
    __shared__ int sh[256];
    int i = blockIdx.x * 256 + threadIdx.x;
    int v = (i < n) ? g_deg[i] : 0;
    if (i < n) g_dinv[i] = (v > 0) ? rsqrtf((float)v) : 0.f;
    sh[threadIdx.x] = v;
    __syncthreads();
    for (int o = 128; o > 0; o >>= 1) {
        if (threadIdx.x < o) sh[threadIdx.x] += sh[threadIdx.x + o];
        __syncthreads();
    }
    if (threadIdx.x == 0) g_blk[blockIdx.x] = sh[0];
}
__global__ void k_scanblk(int nblk) {
    __shared__ int sh[512];
    int t = threadIdx.x;
    int v = (t < nblk) ? g_blk[t] : 0;
    sh[t] = v;
    __syncthreads();
    for (int o = 1; o < 512; o <<= 1) {
        int x = (t >= o) ? sh[t - o] : 0;
        __syncthreads();
        sh[t] += x;
        __syncthreads();
    }
    if (t < nblk) g_blk[t] = sh[t] - v;
}
__global__ void k_scanout(int n) {
    __shared__ int sh[256];
    int t = threadIdx.x;
    int i = blockIdx.x * 256 + t;
    int v = (i < n) ? g_deg[i] : 0;
    sh[t] = v;
    __syncthreads();
    for (int o = 1; o < 256; o <<= 1) {
        int x = (t >= o) ? sh[t - o] : 0;
        __syncthreads();
        sh[t] += x;
        __syncthreads();
    }
    int excl = g_blk[blockIdx.x] + sh[t] - v;
    if (i < n) g_colptr[i] = excl;
    if (i == n - 1) g_colptr[n] = excl + v;
}
__global__ void k_scatter(const void* __restrict__ ei, int E, int n) {
    int e = blockIdx.x * blockDim.x + threadIdx.x;
    if (e < E) {
        int r = load_idx(ei, e);
        int c = load_idx(ei, (long long)E + e);
        if ((unsigned)r >= (unsigned)n || (unsigned)c >= (unsigned)n) return;
        float w = g_dinv[r] * g_dinv[c];
        int p = g_colptr[c] + atomicAdd(&g_cursor[c], 1);
        g_edge[p] = make_int2(r, __float_as_int(w));
    }
}

// ===================== x fp32 -> fp16 conversion =====================
__global__ void k_cvtx(const float* __restrict__ x, __half* __restrict__ xh, int total8) {
    int idx = blockIdx.x * blockDim.x + threadIdx.x;
    if (idx >= total8) return;
    const float4* src = (const float4*)x + 2 * idx;
    float4 v0 = src[0], v1 = src[1];
    union { __half2 h[4]; uint4 u; } pk;
    pk.h[0] = __floats2half2_rn(v0.x, v0.y);
    pk.h[1] = __floats2half2_rn(v0.z, v0.w);
    pk.h[2] = __floats2half2_rn(v1.x, v1.y);
    pk.h[3] = __floats2half2_rn(v1.z, v1.w);
    ((uint4*)xh)[idx] = pk.u;
}

// ===================== weight prep: transpose + fp16 hi/lo split =====================
__global__ void k_prepB(const float* __restrict__ W, int K, int Nj, int nstack, int off) {
    int idx = blockIdx.x * blockDim.x + threadIdx.x;
    int total = nstack * K * Nj;
    if (idx >= total) return;
    int n = idx % Nj;
    int k = (idx / Nj) % K;
    int s = idx / (Nj * K);
    float v = W[idx];
    __half h = __float2half_rn(v);
    __half l = __float2half_rn(v - __half2float(h));
    int o = off + ((s * Nj + n) * K + k);
    g_Bhi[o] = h;
    g_Blo[o] = l;
}

// ===================== fused layer2+proj weights: U_j = W2_j @ fpW_j =====================
// W2: (3, 384, 64); fpW: (192, 64). U stored at BOFF2 as [192, 384] hi/lo.
__global__ void k_prepU(const float* __restrict__ W2, const float* __restrict__ fpW) {
    int idx = blockIdx.x * blockDim.x + threadIdx.x;
    if (idx >= 3 * 384 * 64) return;
    int c = idx & 63;
    int k = (idx >> 6) % 384;
    int j = idx / (384 * 64);
    float s = 0.f;
    for (int t = 0; t < 64; t++)
        s += W2[((size_t)(j * 384 + k)) * 64 + t] * fpW[(size_t)(j * 64 + t) * 64 + c];
    __half h = __float2half_rn(s);
    __half l = __float2half_rn(s - __half2float(h));
    int n = j * 64 + c;
    int o = BOFF2 + n * 384 + k;
    g_Bhi[o] = h;
    g_Blo[o] = l;
}
__global__ void k_prepbf(const float* __restrict__ b2, const float* __restrict__ fpW,
                         const float* __restrict__ fpb) {
    int idx = threadIdx.x;   // 192
    int c = idx & 63, j = idx >> 6;
    float s = (j == 0) ? fpb[c] : 0.f;
    for (int t = 0; t < 64; t++)
        s += b2[j * 64 + t] * fpW[(size_t)(j * 64 + t) * 64 + c];
    g_b2f[idx] = s;
}

// ===================== fp16 HMMA GEMM (8 warps, 64x32 warp tiles, fused hi/lo B x4) =====================
template <int KTOT, int NOUT, int BN, bool FUSE, bool OUT32>
__global__ __launch_bounds__(256, 2)
void k_hgemm(const __half* __restrict__ A,
             const __half* __restrict__ Bhi,
             const __half* __restrict__ Blo,
             const float* __restrict__ bias,
             void* __restrict__ d0, int s0,
             void* __restrict__ d1, int s1,
             void* __restrict__ d2, int s2,
             int nrows)
{
    static_assert(BN == 128 || BN == 64, "");
    constexpr int NC  = KTOT / 32;
    constexpr int STR = 40;
    constexpr int WN  = (BN == 128) ? 4 : 2;
    constexpr int WTM = (BN == 128) ? 64 : 32;
    constexpr int MT  = WTM / 16;
    constexpr int NT  = 4;
    constexpr int A_BYTES = 128 * STR * 2;
    constexpr int B_BYTES = BN * STR * 2;
    constexpr int STAGE = A_BYTES + 2 * B_BYTES;
    constexpr int BPT = BN * 8 / 256;

    extern __shared__ __align__(16) char sm[];

    const int tid  = threadIdx.x;
    const int lane = tid & 31;
    const int w    = tid >> 5;
    const int warp_m = w / WN;
    const int warp_n = w % WN;
    const int rowBase = blockIdx.y * 128;
    const int colBase = blockIdx.x * BN;

    const int arow = tid >> 1;
    const int acb  = tid & 1;
    const int agrow = min(rowBase + arow, nrows - 1);

    uint4 pah[2];

    auto load_A = [&](int c) {
        const uint4* src = (const uint4*)(A + (size_t)agrow * KTOT + c * 32 + acb * 16);
        pah[0] = src[0];
        pah[1] = src[1];
    };
    auto cpasync_B = [&](int c, int s) {
        char* base = sm + s * STAGE + A_BYTES;
#pragma unroll
        for (int j = 0; j < BPT; j++) {
            int idx  = tid + j * 256;
            int arr  = idx / (BN * 4);
            int cidx = idx % (BN * 4);
            int brow = cidx >> 2, bq = cidx & 3;
            const __half* gp = (arr ? Blo : Bhi) +
                               (size_t)(colBase + brow) * KTOT + c * 32 + bq * 8;
            uint32_t sa = smem_u32(base + arr * B_BYTES + brow * 80 + bq * 16);
            asm volatile("cp.async.cg.shared.global [%0], [%1], 16;" :: "r"(sa), "l"(gp));
        }
        asm volatile("cp.async.commit_group;" ::: "memory");
    };
    auto store_A = [&](int c, int s) {
        uint16_t* sA = (uint16_t*)(sm + s * STAGE);
        uint32_t aoff = arow * STR + acb * 16;
        if constexpr (FUSE) {
#pragma unroll
            for (int i = 0; i < 2; i++) {
                uint4 u = pah[i];
                uint32_t* uu = (uint32_t*)&u;
                uint4 o;
                uint32_t* oo = (uint32_t*)&o;
#pragma unroll
                for (int j = 0; j < 4; j++) {
                    int kb = c * 32 + acb * 16 + i * 8 + j * 2;
                    float2 f = __half22float2(*(__half2*)&uu[j]);
                    f.x = fmaxf(fmaf(f.x, g_bnsc[kb + 0], g_bnsh[kb + 0]), 0.f);
                    f.y = fmaxf(fmaf(f.y, g_bnsc[kb + 1], g_bnsh[kb + 1]), 0.f);
                    __half2 h = __floats2half2_rn(f.x, f.y);
                    oo[j] = *(uint32_t*)&h;
                }
                *(uint4*)&sA[aoff + i * 8] = o;
            }
        } else {
            *(uint4*)&sA[aoff]     = pah[0];
            *(uint4*)&sA[aoff + 8] = pah[1];
        }
    };

    float acc[MT][NT][4];
#pragma unroll
    for (int mt = 0; mt < MT; mt++)
#pragma unroll
        for (int nt = 0; nt < NT; nt++)
#pragma unroll
            for (int i = 0; i < 4; i++) acc[mt][nt][i] = 0.f;

    const int arow_lm = warp_m * WTM + (lane & 7) + ((lane >> 3) & 1) * 8;
    const int acol_lm = (lane >> 4) * 8;
    const int brow_lm = warp_n * 32 + (lane & 7);
    const int bcol_lm = ((lane >> 3) & 1) * 8;
    const uint32_t bsel = (lane & 16) ? (uint32_t)(BN * STR) : 0u;

    auto compute = [&](int s) {
        const uint16_t* sA = (const uint16_t*)(sm + s * STAGE);
        const uint16_t* sB = (const uint16_t*)(sm + s * STAGE + A_BYTES) + bsel;
#pragma unroll
        for (int ks = 0; ks < 2; ks++) {
            uint32_t ah[MT][4], bf[NT][4];
#pragma unroll
            for (int mt = 0; mt < MT; mt++) {
                uint32_t addr = smem_u32(&sA[(arow_lm + mt * 16) * STR + acol_lm + ks * 16]);
                asm volatile("ldmatrix.sync.aligned.m8n8.x4.shared.b16 {%0,%1,%2,%3}, [%4];"
                    : "=r"(ah[mt][0]), "=r"(ah[mt][1]), "=r"(ah[mt][2]), "=r"(ah[mt][3]) : "r"(addr));
            }
#pragma unroll
            for (int nt = 0; nt < NT; nt++) {
                uint32_t addr = smem_u32(&sB[(brow_lm + nt * 8) * STR + bcol_lm + ks * 16]);
                asm volatile("ldmatrix.sync.aligned.m8n8.x4.shared.b16 {%0,%1,%2,%3}, [%4];"
                    : "=r"(bf[nt][0]), "=r"(bf[nt][1]), "=r"(bf[nt][2]), "=r"(bf[nt][3]) : "r"(addr));
            }
#pragma unroll
            for (int mt = 0; mt < MT; mt++)
#pragma unroll
                for (int nt = 0; nt < NT; nt++) {
                    asm volatile(
                        "mma.sync.aligned.m16n8k16.row.col.f32.f16.f16.f32 "
                        "{%0,%1,%2,%3}, {%4,%5,%6,%7}, {%8,%9}, {%0,%1,%2,%3};"
                        : "+f"(acc[mt][nt][0]), "+f"(acc[mt][nt][1]),
                          "+f"(acc[mt][nt][2]), "+f"(acc[mt][nt][3])
                        : "r"(ah[mt][0]), "r"(ah[mt][1]), "r"(ah[mt][2]), "r"(ah[mt][3]),
                          "r"(bf[nt][0]), "r"(bf[nt][1]));
                    asm volatile(
                        "mma.sync.aligned.m16n8k16.row.col.f32.f16.f16.f32 "
                        "{%0,%1,%2,%3}, {%4,%5,%6,%7}, {%8,%9}, {%0,%1,%2,%3};"
                        : "+f"(acc[mt][nt][0]), "+f"(acc[mt][nt][1]),
                          "+f"(acc[mt][nt][2]), "+f"(acc[mt][nt][3])
                        : "r"(ah[mt][0]), "r"(ah[mt][1]), "r"(ah[mt][2]), "r"(ah[mt][3]),
                          "r"(bf[nt][2]), "r"(bf[nt][3]));
                }
        }
    };

    // ---- pipeline ----
    cpasync_B(0, 0);
    load_A(0);
    store_A(0, 0);
    asm volatile("cp.async.wait_group 0;" ::: "memory");
    __syncthreads();
    for (int c = 0; c < NC; c++) {
        if (c + 1 < NC) {
            cpasync_B(c + 1, (c + 1) & 1);
            load_A(c + 1);
        }
        compute(c & 1);
        if (c + 1 < NC) {
            store_A(c + 1, (c + 1) & 1);
            asm volatile("cp.async.wait_group 0;" ::: "memory");
        }
        __syncthreads();
    }

    // ---- epilogue ----
    const int g = blockIdx.x;
#pragma unroll
    for (int nt = 0; nt < NT; nt++) {
        int ccol = warp_n * 32 + nt * 8 + (lane & 3) * 2;
        int gcol = colBase + ccol;
        float bx = bias[gcol], by = bias[gcol + 1];
#pragma unroll
        for (int mt = 0; mt < MT; mt++) {
            int r0 = rowBase + warp_m * WTM + mt * 16 + (lane >> 2);
            int r1 = r0 + 8;
            float v00 = acc[mt][nt][0] + bx, v01 = acc[mt][nt][1] + by;
            float v10 = acc[mt][nt][2] + bx, v11 = acc[mt][nt][3] + by;
            if (OUT32 && g == 0) {
                float* dp = (float*)d0;
                if (r0 < nrows) *(float2*)(dp + (size_t)r0 * s0 + ccol) = make_float2(v00, v01);
                if (r1 < nrows) *(float2*)(dp + (size_t)r1 * s0 + ccol) = make_float2(v10, v11);
            } else {
                __half* dp = (__half*)((g == 0) ? d0 : ((g == 1) ? d1 : d2));
                int st = (g == 0) ? s0 : ((g == 1) ? s1 : s2);
                if (r0 < nrows) *(__half2*)(dp + (size_t)r0 * st + ccol) = __floats2half2_rn(v00, v01);
                if (r1 < nrows) *(__half2*)(dp + (size_t)r1 * st + ccol) = __floats2half2_rn(v10, v11);
            }
        }
    }
}

template <int KTOT, int NOUT, int BN, bool FUSE, bool OUT32>
static void launch_hgemm(const __half* A, const __half* bhi, const __half* blo,
                         const float* bias, void* d0, int s0, void* d1, int s1,
                         void* d2, int s2, int nrows) {
    constexpr int STAGE = (128 * 40 * 2) + 2 * (BN * 40 * 2);
    int smem = 2 * STAGE;
    cudaFuncSetAttribute(k_hgemm<KTOT, NOUT, BN, FUSE, OUT32>,
                         cudaFuncAttributeMaxDynamicSharedMemorySize, smem);
    k_hgemm<KTOT, NOUT, BN, FUSE, OUT32><<<dim3(NOUT / BN, (nrows + 127) / 128), 256, smem>>>(
        A, bhi, blo, bias, d0, s0, d1, s1, d2, s2, nrows);
}

// ===================== fused first-hop SpMM (fp16 gather, dual fp16 output) =====================
template <int CW>
__global__ __launch_bounds__(256)
void k_spmm1(const __half* __restrict__ src,
             __half* __restrict__ outA, int sA,
             __half* __restrict__ outB, int n)
{
    constexpr int VL = CW / 32;
    int node = blockIdx.x * 8 + (threadIdx.x >> 5);
    if (node >= n) return;
    int lane = threadIdx.x & 31;
    int s = g_colptr[node];
    int e = g_colptr[node + 1];
    float acc[VL];
#pragma unroll
    for (int i = 0; i < VL; i++) acc[i] = 0.f;

    for (int p = s; p < e; p++) {
        int2  ed = g_edge[p];
        int   r = ed.x;
        float w = __int_as_float(ed.y);
        const __half* hp = src + (size_t)r * CW + lane * VL;
        uint4 u = *(const uint4*)hp;   // VL==8 only used here
        const __half2* h2 = (const __half2*)&u;
#pragma unroll
        for (int i = 0; i < 4; i++) {
            float2 f = __half22float2(h2[i]);
            acc[2 * i]     = fmaf(w, f.x, acc[2 * i]);
            acc[2 * i + 1] = fmaf(w, f.y, acc[2 * i + 1]);
        }
    }
    __half2 hh[VL / 2];
#pragma unroll
    for (int i = 0; i < VL / 2; i++) hh[i] = __floats2half2_rn(acc[2 * i], acc[2 * i + 1]);
    __half* o = (lane < 16) ? (outA + (size_t)node * sA + lane * VL)
                            : (outB + (size_t)node * (CW / 2) + (lane - 16) * VL);
    *(uint4*)o = *(uint4*)hh;
}

// second-hop SpMM: fp16 gather -> fp16 out (CW=128)
template <int CW>
__global__ __launch_bounds__(256)
void k_spmm2(const __half* __restrict__ src, __half* __restrict__ out, int sO, int n)
{
    constexpr int VL = CW / 32;
    int node = blockIdx.x * 8 + (threadIdx.x >> 5);
    if (node >= n) return;
    int lane = threadIdx.x & 31;
    int s = g_colptr[node];
    int e = g_colptr[node + 1];
    float acc[VL];
#pragma unroll
    for (int i = 0; i < VL; i++) acc[i] = 0.f;

    for (int p = s; p < e; p++) {
        int2  ed = g_edge[p];
        int   r = ed.x;
        float w = __int_as_float(ed.y);
        const __half* hp = src + (size_t)r * CW + lane * VL;
        uint2 u = *(const uint2*)hp;   // VL==4
        const __half2* h2 = (const __half2*)&u;
#pragma unroll
        for (int i = 0; i < 2; i++) {
            float2 f = __half22float2(h2[i]);
            acc[2 * i]     = fmaf(w, f.x, acc[2 * i]);
            acc[2 * i + 1] = fmaf(w, f.y, acc[2 * i + 1]);
        }
    }
    __half* o = out + (size_t)node * sO + lane * VL;
    __half2 hh[VL / 2];
#pragma unroll
    for (int i = 0; i < VL / 2; i++) hh[i] = __floats2half2_rn(acc[2 * i], acc[2 * i + 1]);
    *(uint2*)o = *(uint2*)hh;
}

// ===== layer-2 fused-projection SpMMs: accumulate into fp32 out =====
// spmm1acc: src [n,128] = Y1|Y2 fp16. lanes 0-15: out[node,0:64] += gather(Y1);
//           lanes 16-31: outB[node,0:64] fp16 = gather(Y2) (hop2 intermediate).
__global__ __launch_bounds__(256)
void k_spmm1acc(const __half* __restrict__ src,
                float* __restrict__ out,
                __half* __restrict__ outB, int n)
{
    int node = blockIdx.x * 8 + (threadIdx.x >> 5);
    if (node >= n) return;
    int lane = threadIdx.x & 31;
    int s = g_colptr[node];
    int e = g_colptr[node + 1];
    float acc[4] = {0.f, 0.f, 0.f, 0.f};

    for (int p = s; p < e; p++) {
        int2  ed = g_edge[p];
        int   r = ed.x;
        float w = __int_as_float(ed.y);
        const __half* hp = src + (size_t)r * 128 + lane * 4;
        uint2 u = *(const uint2*)hp;
        const __half2* h2 = (const __half2*)&u;
#pragma unroll
        for (int i = 0; i < 2; i++) {
            float2 f = __half22float2(h2[i]);
            acc[2 * i]     = fmaf(w, f.x, acc[2 * i]);
            acc[2 * i + 1] = fmaf(w, f.y, acc[2 * i + 1]);
        }
    }
    if (lane < 16) {
        float* o = out + (size_t)node * 64 + lane * 4;
        float4 v = *(float4*)o;
        v.x += acc[0]; v.y += acc[1]; v.z += acc[2]; v.w += acc[3];
        *(float4*)o = v;
    } else {
        __half* o = outB + (size_t)node * 64 + (lane - 16) * 4;
        __half2 hh[2];
        hh[0] = __floats2half2_rn(acc[0], acc[1]);
        hh[1] = __floats2half2_rn(acc[2], acc[3]);
        *(uint2*)o = *(uint2*)hh;
    }
}

// spmm2acc: src [n,64] fp16 -> out[node,0:64] += gather
__global__ __launch_bounds__(256)
void k_spmm2acc(const __half* __restrict__ src, float* __restrict__ out, int n)
{
    int node = blockIdx.x * 8 + (threadIdx.x >> 5);
    if (node >= n) return;
    int lane = threadIdx.x & 31;
    int s = g_colptr[node];
    int e = g_colptr[node + 1];
    float acc[2] = {0.f, 0.f};

    for (int p = s; p < e; p++) {
        int2  ed = g_edge[p];
        int   r = ed.x;
        float w = __int_as_float(ed.y);
        uint u = *(const uint*)(src + (size_t)r * 64 + lane * 2);
        float2 f = __half22float2(*(const __half2*)&u);
        acc[0] = fmaf(w, f.x, acc[0]);
        acc[1] = fmaf(w, f.y, acc[1]);
    }
    float* o = out + (size_t)node * 64 + lane * 2;
    float2 v = *(float2*)o;
    v.x += acc[0]; v.y += acc[1];
    *(float2*)o = v;
}

// ===================== BatchNorm stats (128-col slice) + finalize =====================
__global__ void k_bnstats(const __half* __restrict__ H, int N, int C, int colOff) {
    int col = colOff + threadIdx.x;
    int r0 = blockIdx.x * 256;
    int r1 = min(r0 + 256, N);
    float s = 0.f, s2 = 0.f;
    for (int r = r0; r < r1; r++) {
        float v = __half2float(H[(size_t)r * C + col]);
        s += v;
        s2 += v * v;
    }
    atomicAdd(&g_bnsum[col], s);
    atomicAdd(&g_bnsq[col],  s2);
}
__global__ void k_bnfin(const float* __restrict__ gma, const float* __restrict__ bet,
                        float invN) {
    int c = threadIdx.x;
    float mu  = g_bnsum[c] * invN;
    float var = g_bnsq[c] * invN - mu * mu;
    float sc  = gma[c] * rsqrtf(var + EPSV);
    g_bnsc[c] = sc;
    g_bnsh[c] = bet[c] - mu * sc;
}

extern "C" void kernel_launch(void* const* d_in, const int* in_sizes, int n_in,
                              void* d_out, int out_size) {
    const float* x    = (const float*)d_in[0];
    const void*  ei   = d_in[1];
    const float* W0   = (const float*)d_in[2];
    const float* b0   = (const float*)d_in[3];
    const float* W1   = (const float*)d_in[4];
    const float* b1   = (const float*)d_in[5];
    const float* W2   = (const float*)d_in[6];
    const float* b2   = (const float*)d_in[7];
    const float* bn0g = (const float*)d_in[8];
    const float* bn0b = (const float*)d_in[9];
    const float* bn1g = (const float*)d_in[10];
    const float* bn1b = (const float*)d_in[11];
    const float* fpW  = (const float*)d_in[12];
    const float* fpb  = (const float*)d_in[13];
    float*       out  = (float*)d_out;

    const int N = in_sizes[0] / 128;
    int E = in_sizes[1] / 2;
    if (E > EMAXC) E = in_sizes[1] / 4;

    int   *deg, *cursor;
    float *bnsum, *bnsq, *b2f;
    __half *tc, *t1h, *hA, *hB, *bhi, *blo;
    cudaGetSymbolAddress((void**)&deg,    g_deg);
    cudaGetSymbolAddress((void**)&cursor, g_cursor);
    cudaGetSymbolAddress((void**)&tc,     g_tc);
    cudaGetSymbolAddress((void**)&t1h,    g_t1h);
    cudaGetSymbolAddress((void**)&hA,     g_hA);
    cudaGetSymbolAddress((void**)&hB,     g_hB);
    cudaGetSymbolAddress((void**)&bnsum,  g_bnsum);
    cudaGetSymbolAddress((void**)&bnsq,   g_bnsq);
    cudaGetSymbolAddress((void**)&b2f,    g_b2f);
    cudaGetSymbolAddress((void**)&bhi,    g_Bhi);
    cudaGetSymbolAddress((void**)&blo,    g_Blo);

    const float invN = 1.f / (float)N;
    const int nblk = (N + 255) / 256;
    const int sb = (N + 7) / 8;

    const bool fork = g_si.ok;
    cudaStream_t sp = fork ? g_si.s1 : (cudaStream_t)0;
    auto forkTo = [&](cudaEvent_t ev) {
        if (fork) { cudaEventRecord(ev, 0); cudaStreamWaitEvent(sp, ev, 0); }
    };
    auto joinFrom = [&](cudaEvent_t ev) {
        if (fork) { cudaEventRecord(ev, sp); cudaStreamWaitEvent(0, ev, 0); }
    };

    // -------- main: minimal critical path to layer-0 GEMM --------
    k_cvtx<<<(N * 128 / 8 + 255) / 256, 256>>>(x, t1h, N * 128 / 8);
    k_prepB<<<(3 * 128 * 128 + 255) / 256, 256>>>(W0, 128, 128, 3, BOFF0);

    // -------- fork: preproc + remaining weight prep on side stream --------
    forkTo(g_si.ev[0]);
    k_detect<<<1, 256, 0, sp>>>((const int*)ei, in_sizes[1]);
    cudaMemsetAsync(deg,    0, (size_t)N * sizeof(int), sp);
    cudaMemsetAsync(cursor, 0, (size_t)N * sizeof(int), sp);
    k_deg<<<(E + 255) / 256, 256, 0, sp>>>(ei, E, N);
    k_blksum<<<nblk, 256, 0, sp>>>(N);
    k_scanblk<<<1, 512, 0, sp>>>(nblk);
    k_scanout<<<nblk, 256, 0, sp>>>(N);
    k_scatter<<<(E + 255) / 256, 256, 0, sp>>>(ei, E, N);
    k_prepB<<<(3 * 384 * 128 + 255) / 256, 256, 0, sp>>>(W1, 384, 128, 3, BOFF1);
    k_prepU<<<(3 * 384 * 64 + 255) / 256, 256, 0, sp>>>(W2, fpW);
    k_prepbf<<<1, 192, 0, sp>>>(b2, fpW, fpb);

    // -------- main: layer-0 GEMM (reads fp16 x), then BN resets --------
    launch_hgemm<128, 384, 128, false, false>(t1h, bhi + BOFF0, blo + BOFF0, b0,
                                              hA, 384, tc, 256, tc + 128, 256, N);
    cudaMemsetAsync(bnsum, 0, 384 * sizeof(float));
    cudaMemsetAsync(bnsq,  0, 384 * sizeof(float));

    // join preproc (spmm needs CSC); fork bnstats(hop0) to side
    joinFrom(g_si.ev[1]);
    forkTo(g_si.ev[2]);
    k_bnstats<<<nblk, 128, 0, sp>>>(hA, N, 384, 0);

    k_spmm1<256><<<sb, 256>>>(tc, hA + 128, 384, t1h, N);
    forkTo(g_si.ev[3]);
    k_bnstats<<<nblk, 128, 0, sp>>>(hA, N, 384, 128);
    k_spmm2<128><<<sb, 256>>>(t1h, hA + 256, 384, N);
    k_bnstats<<<nblk, 128>>>(hA, N, 384, 256);
    joinFrom(g_si.ev[4]);
    k_bnfin<<<1, 384>>>(bn0g, bn0b, invN);
    cudaMemsetAsync(bnsum, 0, 384 * sizeof(float));
    cudaMemsetAsync(bnsq,  0, 384 * sizeof(float));

    // -------- layer 1 (BN0+ReLU fused into A-load) --------
    launch_hgemm<384, 384, 128, true, false>(hA, bhi + BOFF1, blo + BOFF1, b1,
                                             hB, 384, tc, 256, tc + 128, 256, N);
    forkTo(g_si.ev[5]);
    k_bnstats<<<nblk, 128, 0, sp>>>(hB, N, 384, 0);
    k_spmm1<256><<<sb, 256>>>(tc, hB + 128, 384, t1h, N);
    forkTo(g_si.ev[0]);
    k_bnstats<<<nblk, 128, 0, sp>>>(hB, N, 384, 128);
    k_spmm2<128><<<sb, 256>>>(t1h, hB + 256, 384, N);
    k_bnstats<<<nblk, 128>>>(hB, N, 384, 256);
    joinFrom(g_si.ev[1]);
    k_bnfin<<<1, 384>>>(bn1g, bn1b, invN);

    // -------- layer 2 fused with final projection (BN1+ReLU fused in A-load) --------
    // Y0 -> out (fp32, bias b'0+fpb); Y1 -> tc fp16; Y2 -> tc+64 fp16
    launch_hgemm<384, 192, 64, true, true>(hB, bhi + BOFF2, blo + BOFF2, b2f,
                                           out, 64, tc, 128, tc + 64, 128, N);
    // out += A(Y1); t1h = A(Y2)
    k_spmm1acc<<<sb, 256>>>(tc, out, t1h, N);
    // out += A(A(Y2))
    k_spmm2acc<<<sb, 256>>>(t1h, out, N);
}

// round 16
// speedup vs baseline: 1.1067x; 1.0936x over previous
#include <cuda_runtime.h>
#include <cuda_fp16.h>
#include <cstdint>

// ===================== problem constants =====================
static constexpr int NMAXC = 100000;
static constexpr int EMAXC = 1600000;
#define EPSV 1e-5f

// ===================== device scratch (static, no allocs) =====================
__device__ int   g_isI64;
__device__ int   g_deg[NMAXC];
__device__ float g_dinv[NMAXC];
__device__ int   g_colptr[NMAXC + 1];
__device__ int   g_cursor[NMAXC];
__device__ int   g_blk[512];
__device__ __align__(8) int2 g_edge[EMAXC];   // (srcrow, weight-bits)

__device__ __align__(16) __half g_tc[(size_t)NMAXC * 256];   // interleaved hop1pre|hop2pre
__device__ __align__(16) __half g_t1h[(size_t)NMAXC * 128];  // x-fp16 / hop2 intermediate
__device__ __align__(16) __half g_hA[(size_t)NMAXC * 384];   // fp16 activations
__device__ __align__(16) __half g_hB[(size_t)NMAXC * 384];
__device__ float g_bnsum[384];
__device__ float g_bnsq[384];
__device__ float g_bnsc[384];
__device__ float g_bnsh[384];
__device__ float g_b2f[192];                  // fused layer2+proj biases

// transposed fp16-split weights: [NOUT, K] row-major, hi & lo
static constexpr int BW_TOT = 384*128 + 384*384 + 192*384 + 64*192;
__device__ __align__(16) __half g_Bhi[BW_TOT];
__device__ __align__(16) __half g_Blo[BW_TOT];
static constexpr int BOFF0 = 0;
static constexpr int BOFF1 = 384*128;
static constexpr int BOFF2 = BOFF1 + 384*384;   // fused U = W2@fpW, [192, 384]

// ===================== side stream for graph-captured fork/join =====================
namespace {
struct StreamInit {
    cudaStream_t s1 = nullptr;
    cudaEvent_t  ev[6] = {};
    bool ok = false;
    StreamInit() {
        ok = (cudaStreamCreateWithFlags(&s1, cudaStreamNonBlocking) == cudaSuccess);
        for (int i = 0; i < 6 && ok; i++)
            ok = (cudaEventCreateWithFlags(&ev[i], cudaEventDisableTiming) == cudaSuccess);
    }
};
StreamInit g_si;
}

// ===================== helpers =====================
__device__ __forceinline__ uint32_t smem_u32(const void* p) {
    uint32_t a;
    asm("{ .reg .u64 t; cvta.to.shared.u64 t, %1; cvt.u32.u64 %0, t; }" : "=r"(a) : "l"(p));
    return a;
}

// ===================== edge-index format detection =====================
__global__ void k_detect(const int* __restrict__ ei32, int nwords) {
    __shared__ int anyNonZero;
    if (threadIdx.x == 0) anyNonZero = 0;
    __syncthreads();
    int lim = min(nwords, 4096);
    for (int i = 1 + 2 * threadIdx.x; i < lim; i += 2 * blockDim.x)
        if (ei32[i] != 0) anyNonZero = 1;
    __syncthreads();
    if (threadIdx.x == 0) g_isI64 = (anyNonZero == 0) ? 1 : 0;
}
__device__ __forceinline__ int load_idx(const void* ei, long long pos) {
    if (g_isI64) return (int)((const long long*)ei)[pos];
    return ((const int*)ei)[pos];
}

// ===================== graph preprocessing =====================
__global__ void k_deg(const void* __restrict__ ei, int E, int n) {
    int e = blockIdx.x * blockDim.x + threadIdx.x;
    if (e < E) {
        int c = load_idx(ei, (long long)E + e);
        if ((unsigned)c < (unsigned)n) atomicAdd(&g_deg[c], 1);
    }
}
__global__ void k_blksum(int n) {
    __shared__ int sh[256];
    int i = blockIdx.x * 256 + threadIdx.x;
    int v = (i < n) ? g_deg[i] : 0;
    if (i < n) g_dinv[i] = (v > 0) ? rsqrtf((float)v) : 0.f;
    sh[threadIdx.x] = v;
    __syncthreads();
    for (int o = 128; o > 0; o >>= 1) {
        if (threadIdx.x < o) sh[threadIdx.x] += sh[threadIdx.x + o];
        __syncthreads();
    }
    if (threadIdx.x == 0) g_blk[blockIdx.x] = sh[0];
}
__global__ void k_scanblk(int nblk) {
    __shared__ int sh[512];
    int t = threadIdx.x;
    int v = (t < nblk) ? g_blk[t] : 0;
    sh[t] = v;
    __syncthreads();
    for (int o = 1; o < 512; o <<= 1) {
        int x = (t >= o) ? sh[t - o] : 0;
        __syncthreads();
        sh[t] += x;
        __syncthreads();
    }
    if (t < nblk) g_blk[t] = sh[t] - v;
}
__global__ void k_scanout(int n) {
    __shared__ int sh[256];
    int t = threadIdx.x;
    int i = blockIdx.x * 256 + t;
    int v = (i < n) ? g_deg[i] : 0;
    sh[t] = v;
    __syncthreads();
    for (int o = 1; o < 256; o <<= 1) {
        int x = (t >= o) ? sh[t - o] : 0;
        __syncthreads();
        sh[t] += x;
        __syncthreads();
    }
    int excl = g_blk[blockIdx.x] + sh[t] - v;
    if (i < n) g_colptr[i] = excl;
    if (i == n - 1) g_colptr[n] = excl + v;
}
__global__ void k_scatter(const void* __restrict__ ei, int E, int n) {
    int e = blockIdx.x * blockDim.x + threadIdx.x;
    if (e < E) {
        int r = load_idx(ei, e);
        int c = load_idx(ei, (long long)E + e);
        if ((unsigned)r >= (unsigned)n || (unsigned)c >= (unsigned)n) return;
        float w = g_dinv[r] * g_dinv[c];
        int p = g_colptr[c] + atomicAdd(&g_cursor[c], 1);
        g_edge[p] = make_int2(r, __float_as_int(w));
    }
}

// ===================== x fp32 -> fp16 conversion =====================
__global__ void k_cvtx(const float* __restrict__ x, __half* __restrict__ xh, int total8) {
    int idx = blockIdx.x * blockDim.x + threadIdx.x;
    if (idx >= total8) return;
    const float4* src = (const float4*)x + 2 * idx;
    float4 v0 = src[0], v1 = src[1];
    union { __half2 h[4]; uint4 u; } pk;
    pk.h[0] = __floats2half2_rn(v0.x, v0.y);
    pk.h[1] = __floats2half2_rn(v0.z, v0.w);
    pk.h[2] = __floats2half2_rn(v1.x, v1.y);
    pk.h[3] = __floats2half2_rn(v1.z, v1.w);
    ((uint4*)xh)[idx] = pk.u;
}

// ===================== weight prep: transpose + fp16 hi/lo split =====================
__global__ void k_prepB(const float* __restrict__ W, int K, int Nj, int nstack, int off) {
    int idx = blockIdx.x * blockDim.x + threadIdx.x;
    int total = nstack * K * Nj;
    if (idx >= total) return;
    int n = idx % Nj;
    int k = (idx / Nj) % K;
    int s = idx / (Nj * K);
    float v = W[idx];
    __half h = __float2half_rn(v);
    __half l = __float2half_rn(v - __half2float(h));
    int o = off + ((s * Nj + n) * K + k);
    g_Bhi[o] = h;
    g_Blo[o] = l;
}

// ===================== fused layer2+proj weights: U_j = W2_j @ fpW_j =====================
__global__ void k_prepU(const float* __restrict__ W2, const float* __restrict__ fpW) {
    int idx = blockIdx.x * blockDim.x + threadIdx.x;
    if (idx >= 3 * 384 * 64) return;
    int c = idx & 63;
    int k = (idx >> 6) % 384;
    int j = idx / (384 * 64);
    float s = 0.f;
    for (int t = 0; t < 64; t++)
        s += W2[((size_t)(j * 384 + k)) * 64 + t] * fpW[(size_t)(j * 64 + t) * 64 + c];
    __half h = __float2half_rn(s);
    __half l = __float2half_rn(s - __half2float(h));
    int n = j * 64 + c;
    int o = BOFF2 + n * 384 + k;
    g_Bhi[o] = h;
    g_Blo[o] = l;
}
__global__ void k_prepbf(const float* __restrict__ b2, const float* __restrict__ fpW,
                         const float* __restrict__ fpb) {
    int idx = threadIdx.x;
    int c = idx & 63, j = idx >> 6;
    float s = (j == 0) ? fpb[c] : 0.f;
    for (int t = 0; t < 64; t++)
        s += b2[j * 64 + t] * fpW[(size_t)(j * 64 + t) * 64 + c];
    g_b2f[idx] = s;
}

// ===================== fp16 HMMA GEMM (8 warps, 64x32 warp tiles) =====================
// BLO: true = B hi+lo two-pass (higher precision); false = hi-only single pass.
template <int KTOT, int NOUT, int BN, bool FUSE, bool OUT32, bool BLO>
__global__ __launch_bounds__(256, 2)
void k_hgemm(const __half* __restrict__ A,
             const __half* __restrict__ Bhi,
             const __half* __restrict__ Blo,
             const float* __restrict__ bias,
             void* __restrict__ d0, int s0,
             void* __restrict__ d1, int s1,
             void* __restrict__ d2, int s2,
             int nrows)
{
    static_assert(BN == 128 || BN == 64, "");
    constexpr int NC  = KTOT / 32;
    constexpr int STR = 40;
    constexpr int WN  = (BN == 128) ? 4 : 2;
    constexpr int WTM = (BN == 128) ? 64 : 32;
    constexpr int MT  = WTM / 16;
    constexpr int NT  = 4;
    constexpr int A_BYTES = 128 * STR * 2;
    constexpr int B_BYTES = BN * STR * 2;
    constexpr int NBARR = BLO ? 2 : 1;
    constexpr int STAGE = A_BYTES + NBARR * B_BYTES;
    constexpr int BPT = BN * 4 * NBARR / 256;

    extern __shared__ __align__(16) char sm[];

    const int tid  = threadIdx.x;
    const int lane = tid & 31;
    const int w    = tid >> 5;
    const int warp_m = w / WN;
    const int warp_n = w % WN;
    const int rowBase = blockIdx.y * 128;
    const int colBase = blockIdx.x * BN;

    const int arow = tid >> 1;
    const int acb  = tid & 1;
    const int agrow = min(rowBase + arow, nrows - 1);

    uint4 pah[2];

    auto load_A = [&](int c) {
        const uint4* src = (const uint4*)(A + (size_t)agrow * KTOT + c * 32 + acb * 16);
        pah[0] = src[0];
        pah[1] = src[1];
    };
    auto cpasync_B = [&](int c, int s) {
        char* base = sm + s * STAGE + A_BYTES;
#pragma unroll
        for (int j = 0; j < BPT; j++) {
            int idx  = tid + j * 256;
            int arr  = BLO ? (idx / (BN * 4)) : 0;
            int cidx = BLO ? (idx % (BN * 4)) : idx;
            int brow = cidx >> 2, bq = cidx & 3;
            const __half* gp = (arr ? Blo : Bhi) +
                               (size_t)(colBase + brow) * KTOT + c * 32 + bq * 8;
            uint32_t sa = smem_u32(base + arr * B_BYTES + brow * 80 + bq * 16);
            asm volatile("cp.async.cg.shared.global [%0], [%1], 16;" :: "r"(sa), "l"(gp));
        }
        asm volatile("cp.async.commit_group;" ::: "memory");
    };
    auto store_A = [&](int c, int s) {
        uint16_t* sA = (uint16_t*)(sm + s * STAGE);
        uint32_t aoff = arow * STR + acb * 16;
        if constexpr (FUSE) {
#pragma unroll
            for (int i = 0; i < 2; i++) {
                uint4 u = pah[i];
                uint32_t* uu = (uint32_t*)&u;
                uint4 o;
                uint32_t* oo = (uint32_t*)&o;
#pragma unroll
                for (int j = 0; j < 4; j++) {
                    int kb = c * 32 + acb * 16 + i * 8 + j * 2;
                    float2 f = __half22float2(*(__half2*)&uu[j]);
                    f.x = fmaxf(fmaf(f.x, g_bnsc[kb + 0], g_bnsh[kb + 0]), 0.f);
                    f.y = fmaxf(fmaf(f.y, g_bnsc[kb + 1], g_bnsh[kb + 1]), 0.f);
                    __half2 h = __floats2half2_rn(f.x, f.y);
                    oo[j] = *(uint32_t*)&h;
                }
                *(uint4*)&sA[aoff + i * 8] = o;
            }
        } else {
            *(uint4*)&sA[aoff]     = pah[0];
            *(uint4*)&sA[aoff + 8] = pah[1];
        }
    };

    float acc[MT][NT][4];
#pragma unroll
    for (int mt = 0; mt < MT; mt++)
#pragma unroll
        for (int nt = 0; nt < NT; nt++)
#pragma unroll
            for (int i = 0; i < 4; i++) acc[mt][nt][i] = 0.f;

    const int arow_lm = warp_m * WTM + (lane & 7) + ((lane >> 3) & 1) * 8;
    const int acol_lm = (lane >> 4) * 8;
    const int brow_lm = warp_n * 32 + (lane & 7);
    const int bcol_lm = ((lane >> 3) & 1) * 8;
    const uint32_t bsel = (BLO && (lane & 16)) ? (uint32_t)(BN * STR) : 0u;

    auto compute = [&](int s) {
        const uint16_t* sA = (const uint16_t*)(sm + s * STAGE);
        const uint16_t* sB = (const uint16_t*)(sm + s * STAGE + A_BYTES) + bsel;
#pragma unroll
        for (int ks = 0; ks < 2; ks++) {
            uint32_t ah[MT][4];
#pragma unroll
            for (int mt = 0; mt < MT; mt++) {
                uint32_t addr = smem_u32(&sA[(arow_lm + mt * 16) * STR + acol_lm + ks * 16]);
                asm volatile("ldmatrix.sync.aligned.m8n8.x4.shared.b16 {%0,%1,%2,%3}, [%4];"
                    : "=r"(ah[mt][0]), "=r"(ah[mt][1]), "=r"(ah[mt][2]), "=r"(ah[mt][3]) : "r"(addr));
            }
            if constexpr (BLO) {
                uint32_t bf[NT][4];
#pragma unroll
                for (int nt = 0; nt < NT; nt++) {
                    uint32_t addr = smem_u32(&sB[(brow_lm + nt * 8) * STR + bcol_lm + ks * 16]);
                    asm volatile("ldmatrix.sync.aligned.m8n8.x4.shared.b16 {%0,%1,%2,%3}, [%4];"
                        : "=r"(bf[nt][0]), "=r"(bf[nt][1]), "=r"(bf[nt][2]), "=r"(bf[nt][3]) : "r"(addr));
                }
#pragma unroll
                for (int mt = 0; mt < MT; mt++)
#pragma unroll
                    for (int nt = 0; nt < NT; nt++) {
                        asm volatile(
                            "mma.sync.aligned.m16n8k16.row.col.f32.f16.f16.f32 "
                            "{%0,%1,%2,%3}, {%4,%5,%6,%7}, {%8,%9}, {%0,%1,%2,%3};"
                            : "+f"(acc[mt][nt][0]), "+f"(acc[mt][nt][1]),
                              "+f"(acc[mt][nt][2]), "+f"(acc[mt][nt][3])
                            : "r"(ah[mt][0]), "r"(ah[mt][1]), "r"(ah[mt][2]), "r"(ah[mt][3]),
                              "r"(bf[nt][0]), "r"(bf[nt][1]));
                        asm volatile(
                            "mma.sync.aligned.m16n8k16.row.col.f32.f16.f16.f32 "
                            "{%0,%1,%2,%3}, {%4,%5,%6,%7}, {%8,%9}, {%0,%1,%2,%3};"
                            : "+f"(acc[mt][nt][0]), "+f"(acc[mt][nt][1]),
                              "+f"(acc[mt][nt][2]), "+f"(acc[mt][nt][3])
                            : "r"(ah[mt][0]), "r"(ah[mt][1]), "r"(ah[mt][2]), "r"(ah[mt][3]),
                              "r"(bf[nt][2]), "r"(bf[nt][3]));
                    }
            } else {
                uint32_t bf[NT][2];
#pragma unroll
                for (int nt = 0; nt < NT; nt++) {
                    uint32_t addr = smem_u32(&sB[(brow_lm + nt * 8) * STR + bcol_lm + ks * 16]);
                    asm volatile("ldmatrix.sync.aligned.m8n8.x2.shared.b16 {%0,%1}, [%2];"
                        : "=r"(bf[nt][0]), "=r"(bf[nt][1]) : "r"(addr));
                }
#pragma unroll
                for (int mt = 0; mt < MT; mt++)
#pragma unroll
                    for (int nt = 0; nt < NT; nt++) {
                        asm volatile(
                            "mma.sync.aligned.m16n8k16.row.col.f32.f16.f16.f32 "
                            "{%0,%1,%2,%3}, {%4,%5,%6,%7}, {%8,%9}, {%0,%1,%2,%3};"
                            : "+f"(acc[mt][nt][0]), "+f"(acc[mt][nt][1]),
                              "+f"(acc[mt][nt][2]), "+f"(acc[mt][nt][3])
                            : "r"(ah[mt][0]), "r"(ah[mt][1]), "r"(ah[mt][2]), "r"(ah[mt][3]),
                              "r"(bf[nt][0]), "r"(bf[nt][1]));
                    }
            }
        }
    };

    // ---- pipeline ----
    cpasync_B(0, 0);
    load_A(0);
    store_A(0, 0);
    asm volatile("cp.async.wait_group 0;" ::: "memory");
    __syncthreads();
    for (int c = 0; c < NC; c++) {
        if (c + 1 < NC) {
            cpasync_B(c + 1, (c + 1) & 1);
            load_A(c + 1);
        }
        compute(c & 1);
        if (c + 1 < NC) {
            store_A(c + 1, (c + 1) & 1);
            asm volatile("cp.async.wait_group 0;" ::: "memory");
        }
        __syncthreads();
    }

    // ---- epilogue ----
    const int g = blockIdx.x;
#pragma unroll
    for (int nt = 0; nt < NT; nt++) {
        int ccol = warp_n * 32 + nt * 8 + (lane & 3) * 2;
        int gcol = colBase + ccol;
        float bx = bias[gcol], by = bias[gcol + 1];
#pragma unroll
        for (int mt = 0; mt < MT; mt++) {
            int r0 = rowBase + warp_m * WTM + mt * 16 + (lane >> 2);
            int r1 = r0 + 8;
            float v00 = acc[mt][nt][0] + bx, v01 = acc[mt][nt][1] + by;
            float v10 = acc[mt][nt][2] + bx, v11 = acc[mt][nt][3] + by;
            if (OUT32 && g == 0) {
                float* dp = (float*)d0;
                if (r0 < nrows) *(float2*)(dp + (size_t)r0 * s0 + ccol) = make_float2(v00, v01);
                if (r1 < nrows) *(float2*)(dp + (size_t)r1 * s0 + ccol) = make_float2(v10, v11);
            } else {
                __half* dp = (__half*)((g == 0) ? d0 : ((g == 1) ? d1 : d2));
                int st = (g == 0) ? s0 : ((g == 1) ? s1 : s2);
                if (r0 < nrows) *(__half2*)(dp + (size_t)r0 * st + ccol) = __floats2half2_rn(v00, v01);
                if (r1 < nrows) *(__half2*)(dp + (size_t)r1 * st + ccol) = __floats2half2_rn(v10, v11);
            }
        }
    }
}

template <int KTOT, int NOUT, int BN, bool FUSE, bool OUT32, bool BLO>
static void launch_hgemm(const __half* A, const __half* bhi, const __half* blo,
                         const float* bias, void* d0, int s0, void* d1, int s1,
                         void* d2, int s2, int nrows) {
    constexpr int STAGE = (128 * 40 * 2) + (BLO ? 2 : 1) * (BN * 40 * 2);
    int smem = 2 * STAGE;
    cudaFuncSetAttribute(k_hgemm<KTOT, NOUT, BN, FUSE, OUT32, BLO>,
                         cudaFuncAttributeMaxDynamicSharedMemorySize, smem);
    k_hgemm<KTOT, NOUT, BN, FUSE, OUT32, BLO><<<dim3(NOUT / BN, (nrows + 127) / 128), 256, smem>>>(
        A, bhi, blo, bias, d0, s0, d1, s1, d2, s2, nrows);
}

// ===================== fused first-hop SpMM (fp16 gather, dual fp16 output) =====================
template <int CW>
__global__ __launch_bounds__(256)
void k_spmm1(const __half* __restrict__ src,
             __half* __restrict__ outA, int sA,
             __half* __restrict__ outB, int n)
{
    constexpr int VL = CW / 32;
    int node = blockIdx.x * 8 + (threadIdx.x >> 5);
    if (node >= n) return;
    int lane = threadIdx.x & 31;
    int s = g_colptr[node];
    int e = g_colptr[node + 1];
    float acc[VL];
#pragma unroll
    for (int i = 0; i < VL; i++) acc[i] = 0.f;

    for (int p = s; p < e; p++) {
        int2  ed = g_edge[p];
        int   r = ed.x;
        float w = __int_as_float(ed.y);
        const __half* hp = src + (size_t)r * CW + lane * VL;
        uint4 u = *(const uint4*)hp;
        const __half2* h2 = (const __half2*)&u;
#pragma unroll
        for (int i = 0; i < 4; i++) {
            float2 f = __half22float2(h2[i]);
            acc[2 * i]     = fmaf(w, f.x, acc[2 * i]);
            acc[2 * i + 1] = fmaf(w, f.y, acc[2 * i + 1]);
        }
    }
    __half2 hh[VL / 2];
#pragma unroll
    for (int i = 0; i < VL / 2; i++) hh[i] = __floats2half2_rn(acc[2 * i], acc[2 * i + 1]);
    __half* o = (lane < 16) ? (outA + (size_t)node * sA + lane * VL)
                            : (outB + (size_t)node * (CW / 2) + (lane - 16) * VL);
    *(uint4*)o = *(uint4*)hh;
}

template <int CW>
__global__ __launch_bounds__(256)
void k_spmm2(const __half* __restrict__ src, __half* __restrict__ out, int sO, int n)
{
    constexpr int VL = CW / 32;
    int node = blockIdx.x * 8 + (threadIdx.x >> 5);
    if (node >= n) return;
    int lane = threadIdx.x & 31;
    int s = g_colptr[node];
    int e = g_colptr[node + 1];
    float acc[VL];
#pragma unroll
    for (int i = 0; i < VL; i++) acc[i] = 0.f;

    for (int p = s; p < e; p++) {
        int2  ed = g_edge[p];
        int   r = ed.x;
        float w = __int_as_float(ed.y);
        const __half* hp = src + (size_t)r * CW + lane * VL;
        uint2 u = *(const uint2*)hp;
        const __half2* h2 = (const __half2*)&u;
#pragma unroll
        for (int i = 0; i < 2; i++) {
            float2 f = __half22float2(h2[i]);
            acc[2 * i]     = fmaf(w, f.x, acc[2 * i]);
            acc[2 * i + 1] = fmaf(w, f.y, acc[2 * i + 1]);
        }
    }
    __half* o = out + (size_t)node * sO + lane * VL;
    __half2 hh[VL / 2];
#pragma unroll
    for (int i = 0; i < VL / 2; i++) hh[i] = __floats2half2_rn(acc[2 * i], acc[2 * i + 1]);
    *(uint2*)o = *(uint2*)hh;
}

// ===== layer-2 fused-projection SpMMs: accumulate into fp32 out =====
__global__ __launch_bounds__(256)
void k_spmm1acc(const __half* __restrict__ src,
                float* __restrict__ out,
                __half* __restrict__ outB, int n)
{
    int node = blockIdx.x * 8 + (threadIdx.x >> 5);
    if (node >= n) return;
    int lane = threadIdx.x & 31;
    int s = g_colptr[node];
    int e = g_colptr[node + 1];
    float acc[4] = {0.f, 0.f, 0.f, 0.f};

    for (int p = s; p < e; p++) {
        int2  ed = g_edge[p];
        int   r = ed.x;
        float w = __int_as_float(ed.y);
        const __half* hp = src + (size_t)r * 128 + lane * 4;
        uint2 u = *(const uint2*)hp;
        const __half2* h2 = (const __half2*)&u;
#pragma unroll
        for (int i = 0; i < 2; i++) {
            float2 f = __half22float2(h2[i]);
            acc[2 * i]     = fmaf(w, f.x, acc[2 * i]);
            acc[2 * i + 1] = fmaf(w, f.y, acc[2 * i + 1]);
        }
    }
    if (lane < 16) {
        float* o = out + (size_t)node * 64 + lane * 4;
        float4 v = *(float4*)o;
        v.x += acc[0]; v.y += acc[1]; v.z += acc[2]; v.w += acc[3];
        *(float4*)o = v;
    } else {
        __half* o = outB + (size_t)node * 64 + (lane - 16) * 4;
        __half2 hh[2];
        hh[0] = __floats2half2_rn(acc[0], acc[1]);
        hh[1] = __floats2half2_rn(acc[2], acc[3]);
        *(uint2*)o = *(uint2*)hh;
    }
}

__global__ __launch_bounds__(256)
void k_spmm2acc(const __half* __restrict__ src, float* __restrict__ out, int n)
{
    int node = blockIdx.x * 8 + (threadIdx.x >> 5);
    if (node >= n) return;
    int lane = threadIdx.x & 31;
    int s = g_colptr[node];
    int e = g_colptr[node + 1];
    float acc[2] = {0.f, 0.f};

    for (int p = s; p < e; p++) {
        int2  ed = g_edge[p];
        int   r = ed.x;
        float w = __int_as_float(ed.y);
        uint u = *(const uint*)(src + (size_t)r * 64 + lane * 2);
        float2 f = __half22float2(*(const __half2*)&u);
        acc[0] = fmaf(w, f.x, acc[0]);
        acc[1] = fmaf(w, f.y, acc[1]);
    }
    float* o = out + (size_t)node * 64 + lane * 2;
    float2 v = *(float2*)o;
    v.x += acc[0]; v.y += acc[1];
    *(float2*)o = v;
}

// ===================== BatchNorm stats (128-col slice) + finalize =====================
__global__ void k_bnstats(const __half* __restrict__ H, int N, int C, int colOff) {
    int col = colOff + threadIdx.x;
    int r0 = blockIdx.x * 256;
    int r1 = min(r0 + 256, N);
    float s = 0.f, s2 = 0.f;
    for (int r = r0; r < r1; r++) {
        float v = __half2float(H[(size_t)r * C + col]);
        s += v;
        s2 += v * v;
    }
    atomicAdd(&g_bnsum[col], s);
    atomicAdd(&g_bnsq[col],  s2);
}
__global__ void k_bnfin(const float* __restrict__ gma, const float* __restrict__ bet,
                        float invN) {
    int c = threadIdx.x;
    float mu  = g_bnsum[c] * invN;
    float var = g_bnsq[c] * invN - mu * mu;
    float sc  = gma[c] * rsqrtf(var + EPSV);
    g_bnsc[c] = sc;
    g_bnsh[c] = bet[c] - mu * sc;
}

extern "C" void kernel_launch(void* const* d_in, const int* in_sizes, int n_in,
                              void* d_out, int out_size) {
    const float* x    = (const float*)d_in[0];
    const void*  ei   = d_in[1];
    const float* W0   = (const float*)d_in[2];
    const float* b0   = (const float*)d_in[3];
    const float* W1   = (const float*)d_in[4];
    const float* b1   = (const float*)d_in[5];
    const float* W2   = (const float*)d_in[6];
    const float* b2   = (const float*)d_in[7];
    const float* bn0g = (const float*)d_in[8];
    const float* bn0b = (const float*)d_in[9];
    const float* bn1g = (const float*)d_in[10];
    const float* bn1b = (const float*)d_in[11];
    const float* fpW  = (const float*)d_in[12];
    const float* fpb  = (const float*)d_in[13];
    float*       out  = (float*)d_out;

    const int N = in_sizes[0] / 128;
    int E = in_sizes[1] / 2;
    if (E > EMAXC) E = in_sizes[1] / 4;

    int   *deg, *cursor;
    float *bnsum, *bnsq, *b2f;
    __half *tc, *t1h, *hA, *hB, *bhi, *blo;
    cudaGetSymbolAddress((void**)&deg,    g_deg);
    cudaGetSymbolAddress((void**)&cursor, g_cursor);
    cudaGetSymbolAddress((void**)&tc,     g_tc);
    cudaGetSymbolAddress((void**)&t1h,    g_t1h);
    cudaGetSymbolAddress((void**)&hA,     g_hA);
    cudaGetSymbolAddress((void**)&hB,     g_hB);
    cudaGetSymbolAddress((void**)&bnsum,  g_bnsum);
    cudaGetSymbolAddress((void**)&bnsq,   g_bnsq);
    cudaGetSymbolAddress((void**)&b2f,    g_b2f);
    cudaGetSymbolAddress((void**)&bhi,    g_Bhi);
    cudaGetSymbolAddress((void**)&blo,    g_Blo);

    const float invN = 1.f / (float)N;
    const int nblk = (N + 255) / 256;
    const int sb = (N + 7) / 8;

    const bool fork = g_si.ok;
    cudaStream_t sp = fork ? g_si.s1 : (cudaStream_t)0;
    auto forkTo = [&](cudaEvent_t ev) {
        if (fork) { cudaEventRecord(ev, 0); cudaStreamWaitEvent(sp, ev, 0); }
    };
    auto joinFrom = [&](cudaEvent_t ev) {
        if (fork) { cudaEventRecord(ev, sp); cudaStreamWaitEvent(0, ev, 0); }
    };

    // -------- main: minimal critical path to layer-0 GEMM --------
    k_cvtx<<<(N * 128 / 8 + 255) / 256, 256>>>(x, t1h, N * 128 / 8);
    k_prepB<<<(3 * 128 * 128 + 255) / 256, 256>>>(W0, 128, 128, 3, BOFF0);

    // -------- fork: preproc + remaining weight prep on side stream --------
    forkTo(g_si.ev[0]);
    k_detect<<<1, 256, 0, sp>>>((const int*)ei, in_sizes[1]);
    cudaMemsetAsync(deg,    0, (size_t)N * sizeof(int), sp);
    cudaMemsetAsync(cursor, 0, (size_t)N * sizeof(int), sp);
    k_deg<<<(E + 255) / 256, 256, 0, sp>>>(ei, E, N);
    k_blksum<<<nblk, 256, 0, sp>>>(N);
    k_scanblk<<<1, 512, 0, sp>>>(nblk);
    k_scanout<<<nblk, 256, 0, sp>>>(N);
    k_scatter<<<(E + 255) / 256, 256, 0, sp>>>(ei, E, N);
    k_prepB<<<(3 * 384 * 128 + 255) / 256, 256, 0, sp>>>(W1, 384, 128, 3, BOFF1);
    k_prepU<<<(3 * 384 * 64 + 255) / 256, 256, 0, sp>>>(W2, fpW);
    k_prepbf<<<1, 192, 0, sp>>>(b2, fpW, fpb);

    // -------- main: layer-0 GEMM (B hi-only; BN0 absorbs quantization) --------
    launch_hgemm<128, 384, 128, false, false, false>(t1h, bhi + BOFF0, blo + BOFF0, b0,
                                                     hA, 384, tc, 256, tc + 128, 256, N);
    cudaMemsetAsync(bnsum, 0, 384 * sizeof(float));
    cudaMemsetAsync(bnsq,  0, 384 * sizeof(float));

    // join preproc (spmm needs CSC); fork bnstats(hop0) to side
    joinFrom(g_si.ev[1]);
    forkTo(g_si.ev[2]);
    k_bnstats<<<nblk, 128, 0, sp>>>(hA, N, 384, 0);

    k_spmm1<256><<<sb, 256>>>(tc, hA + 128, 384, t1h, N);
    forkTo(g_si.ev[3]);
    k_bnstats<<<nblk, 128, 0, sp>>>(hA, N, 384, 128);
    k_spmm2<128><<<sb, 256>>>(t1h, hA + 256, 384, N);
    k_bnstats<<<nblk, 128>>>(hA, N, 384, 256);
    joinFrom(g_si.ev[4]);
    k_bnfin<<<1, 384>>>(bn0g, bn0b, invN);
    cudaMemsetAsync(bnsum, 0, 384 * sizeof(float));
    cudaMemsetAsync(bnsq,  0, 384 * sizeof(float));

    // -------- layer 1 (BN0+ReLU fused; B hi-only; BN1 absorbs quantization) --------
    launch_hgemm<384, 384, 128, true, false, false>(hA, bhi + BOFF1, blo + BOFF1, b1,
                                                    hB, 384, tc, 256, tc + 128, 256, N);
    forkTo(g_si.ev[5]);
    k_bnstats<<<nblk, 128, 0, sp>>>(hB, N, 384, 0);
    k_spmm1<256><<<sb, 256>>>(tc, hB + 128, 384, t1h, N);
    forkTo(g_si.ev[0]);
    k_bnstats<<<nblk, 128, 0, sp>>>(hB, N, 384, 128);
    k_spmm2<128><<<sb, 256>>>(t1h, hB + 256, 384, N);
    k_bnstats<<<nblk, 128>>>(hB, N, 384, 256);
    joinFrom(g_si.ev[1]);
    k_bnfin<<<1, 384>>>(bn1g, bn1b, invN);

    // -------- layer 2 fused with final projection (B hi+lo, feeds output) --------
    launch_hgemm<384, 192, 64, true, true, true>(hB, bhi + BOFF2, blo + BOFF2, b2f,
                                                 out, 64, tc, 128, tc + 64, 128, N);
    k_spmm1acc<<<sb, 256>>>(tc, out, t1h, N);
    k_spmm2acc<<<sb, 256>>>(t1h, out, N);
}

// round 17
// speedup vs baseline: 1.1273x; 1.0186x over previous
#include <cuda_runtime.h>
#include <cuda_fp16.h>
#include <cstdint>

// ===================== problem constants =====================
static constexpr int NMAXC = 100000;
static constexpr int EMAXC = 1600000;
#define EPSV 1e-5f

// ===================== device scratch (static, no allocs) =====================
__device__ int   g_isI64;
__device__ int   g_deg[NMAXC];
__device__ float g_dinv[NMAXC];
__device__ int   g_colptr[NMAXC + 1];
__device__ int   g_cursor[NMAXC];
__device__ int   g_blk[512];
__device__ __align__(8) int2 g_edge[EMAXC];   // (srcrow, weight-bits)

__device__ __align__(16) __half g_tc[(size_t)NMAXC * 256];   // interleaved hop1pre|hop2pre
__device__ __align__(16) __half g_t1h[(size_t)NMAXC * 128];  // x-fp16 / hop2 intermediate
__device__ __align__(16) __half g_hA[(size_t)NMAXC * 384];   // fp16 activations
__device__ __align__(16) __half g_hB[(size_t)NMAXC * 384];
__device__ float g_bnsum[384];
__device__ float g_bnsq[384];
__device__ float g_bnsc[384];
__device__ float g_bnsh[384];
__device__ float g_b2f[192];                  // fused layer2+proj biases

// transposed fp16-split weights: [NOUT, K] row-major, hi & lo
static constexpr int BW_TOT = 384*128 + 384*384 + 192*384 + 64*192;
__device__ __align__(16) __half g_Bhi[BW_TOT];
__device__ __align__(16) __half g_Blo[BW_TOT];
static constexpr int BOFF0 = 0;
static constexpr int BOFF1 = 384*128;
static constexpr int BOFF2 = BOFF1 + 384*384;   // fused U = W2@fpW, [192, 384]

// ===================== side stream for graph-captured fork/join =====================
namespace {
struct StreamInit {
    cudaStream_t s1 = nullptr;
    cudaEvent_t  ev[6] = {};
    bool ok = false;
    StreamInit() {
        ok = (cudaStreamCreateWithFlags(&s1, cudaStreamNonBlocking) == cudaSuccess);
        for (int i = 0; i < 6 && ok; i++)
            ok = (cudaEventCreateWithFlags(&ev[i], cudaEventDisableTiming) == cudaSuccess);
    }
};
StreamInit g_si;
}

// ===================== helpers =====================
__device__ __forceinline__ uint32_t smem_u32(const void* p) {
    uint32_t a;
    asm("{ .reg .u64 t; cvta.to.shared.u64 t, %1; cvt.u32.u64 %0, t; }" : "=r"(a) : "l"(p));
    return a;
}

// ===================== edge-index format detection =====================
__global__ void k_detect(const int* __restrict__ ei32, int nwords) {
    __shared__ int anyNonZero;
    if (threadIdx.x == 0) anyNonZero = 0;
    __syncthreads();
    int lim = min(nwords, 4096);
    for (int i = 1 + 2 * threadIdx.x; i < lim; i += 2 * blockDim.x)
        if (ei32[i] != 0) anyNonZero = 1;
    __syncthreads();
    if (threadIdx.x == 0) g_isI64 = (anyNonZero == 0) ? 1 : 0;
}
__device__ __forceinline__ int load_idx(const void* ei, long long pos) {
    if (g_isI64) return (int)((const long long*)ei)[pos];
    return ((const int*)ei)[pos];
}

// ===================== graph preprocessing =====================
__global__ void k_deg(const void* __restrict__ ei, int E, int n) {
    int e = blockIdx.x * blockDim.x + threadIdx.x;
    if (e < E) {
        int c = load_idx(ei, (long long)E + e);
        if ((unsigned)c < (unsigned)n) atomicAdd(&g_deg[c], 1);
    }
}
__global__ void k_blksum(int n) {
    __shared__ int sh[256];
    int i = blockIdx.x * 256 + threadIdx.x;
    int v = (i < n) ? g_deg[i] : 0;
    if (i < n) g_dinv[i] = (v > 0) ? rsqrtf((float)v) : 0.f;
    sh[threadIdx.x] = v;
    __syncthreads();
    for (int o = 128; o > 0; o >>= 1) {
        if (threadIdx.x < o) sh[threadIdx.x] += sh[threadIdx.x + o];
        __syncthreads();
    }
    if (threadIdx.x == 0) g_blk[blockIdx.x] = sh[0];
}
__global__ void k_scanblk(int nblk) {
    __shared__ int sh[512];
    int t = threadIdx.x;
    int v = (t < nblk) ? g_blk[t] : 0;
    sh[t] = v;
    __syncthreads();
    for (int o = 1; o < 512; o <<= 1) {
        int x = (t >= o) ? sh[t - o] : 0;
        __syncthreads();
        sh[t] += x;
        __syncthreads();
    }
    if (t < nblk) g_blk[t] = sh[t] - v;
}
__global__ void k_scanout(int n) {
    __shared__ int sh[256];
    int t = threadIdx.x;
    int i = blockIdx.x * 256 + t;
    int v = (i < n) ? g_deg[i] : 0;
    sh[t] = v;
    __syncthreads();
    for (int o = 1; o < 256; o <<= 1) {
        int x = (t >= o) ? sh[t - o] : 0;
        __syncthreads();
        sh[t] += x;
        __syncthreads();
    }
    int excl = g_blk[blockIdx.x] + sh[t] - v;
    if (i < n) g_colptr[i] = excl;
    if (i == n - 1) g_colptr[n] = excl + v;
}
__global__ void k_scatter(const void* __restrict__ ei, int E, int n) {
    int e = blockIdx.x * blockDim.x + threadIdx.x;
    if (e < E) {
        int r = load_idx(ei, e);
        int c = load_idx(ei, (long long)E + e);
        if ((unsigned)r >= (unsigned)n || (unsigned)c >= (unsigned)n) return;
        float w = g_dinv[r] * g_dinv[c];
        int p = g_colptr[c] + atomicAdd(&g_cursor[c], 1);
        g_edge[p] = make_int2(r, __float_as_int(w));
    }
}

// ===================== x fp32 -> fp16 conversion =====================
__global__ void k_cvtx(const float* __restrict__ x, __half* __restrict__ xh, int total8) {
    int idx = blockIdx.x * blockDim.x + threadIdx.x;
    if (idx >= total8) return;
    const float4* src = (const float4*)x + 2 * idx;
    float4 v0 = src[0], v1 = src[1];
    union { __half2 h[4]; uint4 u; } pk;
    pk.h[0] = __floats2half2_rn(v0.x, v0.y);
    pk.h[1] = __floats2half2_rn(v0.z, v0.w);
    pk.h[2] = __floats2half2_rn(v1.x, v1.y);
    pk.h[3] = __floats2half2_rn(v1.z, v1.w);
    ((uint4*)xh)[idx] = pk.u;
}

// ===================== weight prep: transpose + fp16 hi/lo split =====================
__global__ void k_prepB(const float* __restrict__ W, int K, int Nj, int nstack, int off) {
    int idx = blockIdx.x * blockDim.x + threadIdx.x;
    int total = nstack * K * Nj;
    if (idx >= total) return;
    int n = idx % Nj;
    int k = (idx / Nj) % K;
    int s = idx / (Nj * K);
    float v = W[idx];
    __half h = __float2half_rn(v);
    __half l = __float2half_rn(v - __half2float(h));
    int o = off + ((s * Nj + n) * K + k);
    g_Bhi[o] = h;
    g_Blo[o] = l;
}

// ===================== fused layer2+proj weights: U_j = W2_j @ fpW_j =====================
__global__ void k_prepU(const float* __restrict__ W2, const float* __restrict__ fpW) {
    int idx = blockIdx.x * blockDim.x + threadIdx.x;
    if (idx >= 3 * 384 * 64) return;
    int c = idx & 63;
    int k = (idx >> 6) % 384;
    int j = idx / (384 * 64);
    float s = 0.f;
    for (int t = 0; t < 64; t++)
        s += W2[((size_t)(j * 384 + k)) * 64 + t] * fpW[(size_t)(j * 64 + t) * 64 + c];
    __half h = __float2half_rn(s);
    __half l = __float2half_rn(s - __half2float(h));
    int n = j * 64 + c;
    int o = BOFF2 + n * 384 + k;
    g_Bhi[o] = h;
    g_Blo[o] = l;
}
__global__ void k_prepbf(const float* __restrict__ b2, const float* __restrict__ fpW,
                         const float* __restrict__ fpb) {
    int idx = threadIdx.x;
    int c = idx & 63, j = idx >> 6;
    float s = (j == 0) ? fpb[c] : 0.f;
    for (int t = 0; t < 64; t++)
        s += b2[j * 64 + t] * fpW[(size_t)(j * 64 + t) * 64 + c];
    g_b2f[idx] = s;
}

// ===================== fp16 HMMA GEMM (8 warps, 64x32 warp tiles) =====================
// BLO: true = B hi+lo two-pass; false = hi-only single pass.
template <int KTOT, int NOUT, int BN, bool FUSE, bool OUT32, bool BLO>
__global__ __launch_bounds__(256, 2)
void k_hgemm(const __half* __restrict__ A,
             const __half* __restrict__ Bhi,
             const __half* __restrict__ Blo,
             const float* __restrict__ bias,
             void* __restrict__ d0, int s0,
             void* __restrict__ d1, int s1,
             void* __restrict__ d2, int s2,
             int nrows)
{
    static_assert(BN == 128 || BN == 64, "");
    constexpr int NC  = KTOT / 32;
    constexpr int STR = 40;
    constexpr int WN  = (BN == 128) ? 4 : 2;
    constexpr int WTM = (BN == 128) ? 64 : 32;
    constexpr int MT  = WTM / 16;
    constexpr int NT  = 4;
    constexpr int A_BYTES = 128 * STR * 2;
    constexpr int B_BYTES = BN * STR * 2;
    constexpr int NBARR = BLO ? 2 : 1;
    constexpr int STAGE = A_BYTES + NBARR * B_BYTES;
    constexpr int BPT = BN * 4 * NBARR / 256;

    extern __shared__ __align__(16) char sm[];

    const int tid  = threadIdx.x;
    const int lane = tid & 31;
    const int w    = tid >> 5;
    const int warp_m = w / WN;
    const int warp_n = w % WN;
    const int rowBase = blockIdx.y * 128;
    const int colBase = blockIdx.x * BN;

    const int arow = tid >> 1;
    const int acb  = tid & 1;
    const int agrow = min(rowBase + arow, nrows - 1);

    uint4 pah[2];

    auto load_A = [&](int c) {
        const uint4* src = (const uint4*)(A + (size_t)agrow * KTOT + c * 32 + acb * 16);
        pah[0] = src[0];
        pah[1] = src[1];
    };
    auto cpasync_B = [&](int c, int s) {
        char* base = sm + s * STAGE + A_BYTES;
#pragma unroll
        for (int j = 0; j < BPT; j++) {
            int idx  = tid + j * 256;
            int arr  = BLO ? (idx / (BN * 4)) : 0;
            int cidx = BLO ? (idx % (BN * 4)) : idx;
            int brow = cidx >> 2, bq = cidx & 3;
            const __half* gp = (arr ? Blo : Bhi) +
                               (size_t)(colBase + brow) * KTOT + c * 32 + bq * 8;
            uint32_t sa = smem_u32(base + arr * B_BYTES + brow * 80 + bq * 16);
            asm volatile("cp.async.cg.shared.global [%0], [%1], 16;" :: "r"(sa), "l"(gp));
        }
        asm volatile("cp.async.commit_group;" ::: "memory");
    };
    auto store_A = [&](int c, int s) {
        uint16_t* sA = (uint16_t*)(sm + s * STAGE);
        uint32_t aoff = arow * STR + acb * 16;
        if constexpr (FUSE) {
#pragma unroll
            for (int i = 0; i < 2; i++) {
                uint4 u = pah[i];
                uint32_t* uu = (uint32_t*)&u;
                uint4 o;
                uint32_t* oo = (uint32_t*)&o;
#pragma unroll
                for (int j = 0; j < 4; j++) {
                    int kb = c * 32 + acb * 16 + i * 8 + j * 2;
                    float2 f = __half22float2(*(__half2*)&uu[j]);
                    f.x = fmaxf(fmaf(f.x, g_bnsc[kb + 0], g_bnsh[kb + 0]), 0.f);
                    f.y = fmaxf(fmaf(f.y, g_bnsc[kb + 1], g_bnsh[kb + 1]), 0.f);
                    __half2 h = __floats2half2_rn(f.x, f.y);
                    oo[j] = *(uint32_t*)&h;
                }
                *(uint4*)&sA[aoff + i * 8] = o;
            }
        } else {
            *(uint4*)&sA[aoff]     = pah[0];
            *(uint4*)&sA[aoff + 8] = pah[1];
        }
    };

    float acc[MT][NT][4];
#pragma unroll
    for (int mt = 0; mt < MT; mt++)
#pragma unroll
        for (int nt = 0; nt < NT; nt++)
#pragma unroll
            for (int i = 0; i < 4; i++) acc[mt][nt][i] = 0.f;

    const int arow_lm = warp_m * WTM + (lane & 7) + ((lane >> 3) & 1) * 8;
    const int acol_lm = (lane >> 4) * 8;
    const int brow_lm = warp_n * 32 + (lane & 7);
    const int bcol_lm = ((lane >> 3) & 1) * 8;
    const uint32_t bsel = (BLO && (lane & 16)) ? (uint32_t)(BN * STR) : 0u;

    auto compute = [&](int s) {
        const uint16_t* sA = (const uint16_t*)(sm + s * STAGE);
        const uint16_t* sB = (const uint16_t*)(sm + s * STAGE + A_BYTES) + bsel;
#pragma unroll
        for (int ks = 0; ks < 2; ks++) {
            uint32_t ah[MT][4];
#pragma unroll
            for (int mt = 0; mt < MT; mt++) {
                uint32_t addr = smem_u32(&sA[(arow_lm + mt * 16) * STR + acol_lm + ks * 16]);
                asm volatile("ldmatrix.sync.aligned.m8n8.x4.shared.b16 {%0,%1,%2,%3}, [%4];"
                    : "=r"(ah[mt][0]), "=r"(ah[mt][1]), "=r"(ah[mt][2]), "=r"(ah[mt][3]) : "r"(addr));
            }
            if constexpr (BLO) {
                uint32_t bf[NT][4];
#pragma unroll
                for (int nt = 0; nt < NT; nt++) {
                    uint32_t addr = smem_u32(&sB[(brow_lm + nt * 8) * STR + bcol_lm + ks * 16]);
                    asm volatile("ldmatrix.sync.aligned.m8n8.x4.shared.b16 {%0,%1,%2,%3}, [%4];"
                        : "=r"(bf[nt][0]), "=r"(bf[nt][1]), "=r"(bf[nt][2]), "=r"(bf[nt][3]) : "r"(addr));
                }
#pragma unroll
                for (int mt = 0; mt < MT; mt++)
#pragma unroll
                    for (int nt = 0; nt < NT; nt++) {
                        asm volatile(
                            "mma.sync.aligned.m16n8k16.row.col.f32.f16.f16.f32 "
                            "{%0,%1,%2,%3}, {%4,%5,%6,%7}, {%8,%9}, {%0,%1,%2,%3};"
                            : "+f"(acc[mt][nt][0]), "+f"(acc[mt][nt][1]),
                              "+f"(acc[mt][nt][2]), "+f"(acc[mt][nt][3])
                            : "r"(ah[mt][0]), "r"(ah[mt][1]), "r"(ah[mt][2]), "r"(ah[mt][3]),
                              "r"(bf[nt][0]), "r"(bf[nt][1]));
                        asm volatile(
                            "mma.sync.aligned.m16n8k16.row.col.f32.f16.f16.f32 "
                            "{%0,%1,%2,%3}, {%4,%5,%6,%7}, {%8,%9}, {%0,%1,%2,%3};"
                            : "+f"(acc[mt][nt][0]), "+f"(acc[mt][nt][1]),
                              "+f"(acc[mt][nt][2]), "+f"(acc[mt][nt][3])
                            : "r"(ah[mt][0]), "r"(ah[mt][1]), "r"(ah[mt][2]), "r"(ah[mt][3]),
                              "r"(bf[nt][2]), "r"(bf[nt][3]));
                    }
            } else {
                uint32_t bf[NT][2];
#pragma unroll
                for (int nt = 0; nt < NT; nt++) {
                    uint32_t addr = smem_u32(&sB[(brow_lm + nt * 8) * STR + bcol_lm + ks * 16]);
                    asm volatile("ldmatrix.sync.aligned.m8n8.x2.shared.b16 {%0,%1}, [%2];"
                        : "=r"(bf[nt][0]), "=r"(bf[nt][1]) : "r"(addr));
                }
#pragma unroll
                for (int mt = 0; mt < MT; mt++)
#pragma unroll
                    for (int nt = 0; nt < NT; nt++) {
                        asm volatile(
                            "mma.sync.aligned.m16n8k16.row.col.f32.f16.f16.f32 "
                            "{%0,%1,%2,%3}, {%4,%5,%6,%7}, {%8,%9}, {%0,%1,%2,%3};"
                            : "+f"(acc[mt][nt][0]), "+f"(acc[mt][nt][1]),
                              "+f"(acc[mt][nt][2]), "+f"(acc[mt][nt][3])
                            : "r"(ah[mt][0]), "r"(ah[mt][1]), "r"(ah[mt][2]), "r"(ah[mt][3]),
                              "r"(bf[nt][0]), "r"(bf[nt][1]));
                    }
            }
        }
    };

    // ---- pipeline ----
    cpasync_B(0, 0);
    load_A(0);
    store_A(0, 0);
    asm volatile("cp.async.wait_group 0;" ::: "memory");
    __syncthreads();
    for (int c = 0; c < NC; c++) {
        if (c + 1 < NC) {
            cpasync_B(c + 1, (c + 1) & 1);
            load_A(c + 1);
        }
        compute(c & 1);
        if (c + 1 < NC) {
            store_A(c + 1, (c + 1) & 1);
            asm volatile("cp.async.wait_group 0;" ::: "memory");
        }
        __syncthreads();
    }

    // ---- epilogue ----
    const int g = blockIdx.x;
#pragma unroll
    for (int nt = 0; nt < NT; nt++) {
        int ccol = warp_n * 32 + nt * 8 + (lane & 3) * 2;
        int gcol = colBase + ccol;
        float bx = bias[gcol], by = bias[gcol + 1];
#pragma unroll
        for (int mt = 0; mt < MT; mt++) {
            int r0 = rowBase + warp_m * WTM + mt * 16 + (lane >> 2);
            int r1 = r0 + 8;
            float v00 = acc[mt][nt][0] + bx, v01 = acc[mt][nt][1] + by;
            float v10 = acc[mt][nt][2] + bx, v11 = acc[mt][nt][3] + by;
            if (OUT32 && g == 0) {
                float* dp = (float*)d0;
                if (r0 < nrows) *(float2*)(dp + (size_t)r0 * s0 + ccol) = make_float2(v00, v01);
                if (r1 < nrows) *(float2*)(dp + (size_t)r1 * s0 + ccol) = make_float2(v10, v11);
            } else {
                __half* dp = (__half*)((g == 0) ? d0 : ((g == 1) ? d1 : d2));
                int st = (g == 0) ? s0 : ((g == 1) ? s1 : s2);
                if (r0 < nrows) *(__half2*)(dp + (size_t)r0 * st + ccol) = __floats2half2_rn(v00, v01);
                if (r1 < nrows) *(__half2*)(dp + (size_t)r1 * st + ccol) = __floats2half2_rn(v10, v11);
            }
        }
    }
}

template <int KTOT, int NOUT, int BN, bool FUSE, bool OUT32, bool BLO>
static void launch_hgemm(const __half* A, const __half* bhi, const __half* blo,
                         const float* bias, void* d0, int s0, void* d1, int s1,
                         void* d2, int s2, int nrows) {
    constexpr int STAGE = (128 * 40 * 2) + (BLO ? 2 : 1) * (BN * 40 * 2);
    int smem = 2 * STAGE;
    cudaFuncSetAttribute(k_hgemm<KTOT, NOUT, BN, FUSE, OUT32, BLO>,
                         cudaFuncAttributeMaxDynamicSharedMemorySize, smem);
    k_hgemm<KTOT, NOUT, BN, FUSE, OUT32, BLO><<<dim3(NOUT / BN, (nrows + 127) / 128), 256, smem>>>(
        A, bhi, blo, bias, d0, s0, d1, s1, d2, s2, nrows);
}

// ===================== fused first-hop SpMM (fp16 gather, dual fp16 output) =====================
template <int CW>
__global__ __launch_bounds__(256)
void k_spmm1(const __half* __restrict__ src,
             __half* __restrict__ outA, int sA,
             __half* __restrict__ outB, int n)
{
    constexpr int VL = CW / 32;
    int node = blockIdx.x * 8 + (threadIdx.x >> 5);
    if (node >= n) return;
    int lane = threadIdx.x & 31;
    int s = g_colptr[node];
    int e = g_colptr[node + 1];
    float acc[VL];
#pragma unroll
    for (int i = 0; i < VL; i++) acc[i] = 0.f;

    for (int p = s; p < e; p++) {
        int2  ed = g_edge[p];
        int   r = ed.x;
        float w = __int_as_float(ed.y);
        const __half* hp = src + (size_t)r * CW + lane * VL;
        uint4 u = *(const uint4*)hp;
        const __half2* h2 = (const __half2*)&u;
#pragma unroll
        for (int i = 0; i < 4; i++) {
            float2 f = __half22float2(h2[i]);
            acc[2 * i]     = fmaf(w, f.x, acc[2 * i]);
            acc[2 * i + 1] = fmaf(w, f.y, acc[2 * i + 1]);
        }
    }
    __half2 hh[VL / 2];
#pragma unroll
    for (int i = 0; i < VL / 2; i++) hh[i] = __floats2half2_rn(acc[2 * i], acc[2 * i + 1]);
    __half* o = (lane < 16) ? (outA + (size_t)node * sA + lane * VL)
                            : (outB + (size_t)node * (CW / 2) + (lane - 16) * VL);
    *(uint4*)o = *(uint4*)hh;
}

template <int CW>
__global__ __launch_bounds__(256)
void k_spmm2(const __half* __restrict__ src, __half* __restrict__ out, int sO, int n)
{
    constexpr int VL = CW / 32;
    int node = blockIdx.x * 8 + (threadIdx.x >> 5);
    if (node >= n) return;
    int lane = threadIdx.x & 31;
    int s = g_colptr[node];
    int e = g_colptr[node + 1];
    float acc[VL];
#pragma unroll
    for (int i = 0; i < VL; i++) acc[i] = 0.f;

    for (int p = s; p < e; p++) {
        int2  ed = g_edge[p];
        int   r = ed.x;
        float w = __int_as_float(ed.y);
        const __half* hp = src + (size_t)r * CW + lane * VL;
        uint2 u = *(const uint2*)hp;
        const __half2* h2 = (const __half2*)&u;
#pragma unroll
        for (int i = 0; i < 2; i++) {
            float2 f = __half22float2(h2[i]);
            acc[2 * i]     = fmaf(w, f.x, acc[2 * i]);
            acc[2 * i + 1] = fmaf(w, f.y, acc[2 * i + 1]);
        }
    }
    __half* o = out + (size_t)node * sO + lane * VL;
    __half2 hh[VL / 2];
#pragma unroll
    for (int i = 0; i < VL / 2; i++) hh[i] = __floats2half2_rn(acc[2 * i], acc[2 * i + 1]);
    *(uint2*)o = *(uint2*)hh;
}

// ===== layer-2 fused-projection SpMMs: accumulate into fp32 out =====
__global__ __launch_bounds__(256)
void k_spmm1acc(const __half* __restrict__ src,
                float* __restrict__ out,
                __half* __restrict__ outB, int n)
{
    int node = blockIdx.x * 8 + (threadIdx.x >> 5);
    if (node >= n) return;
    int lane = threadIdx.x & 31;
    int s = g_colptr[node];
    int e = g_colptr[node + 1];
    float acc[4] = {0.f, 0.f, 0.f, 0.f};

    for (int p = s; p < e; p++) {
        int2  ed = g_edge[p];
        int   r = ed.x;
        float w = __int_as_float(ed.y);
        const __half* hp = src + (size_t)r * 128 + lane * 4;
        uint2 u = *(const uint2*)hp;
        const __half2* h2 = (const __half2*)&u;
#pragma unroll
        for (int i = 0; i < 2; i++) {
            float2 f = __half22float2(h2[i]);
            acc[2 * i]     = fmaf(w, f.x, acc[2 * i]);
            acc[2 * i + 1] = fmaf(w, f.y, acc[2 * i + 1]);
        }
    }
    if (lane < 16) {
        float* o = out + (size_t)node * 64 + lane * 4;
        float4 v = *(float4*)o;
        v.x += acc[0]; v.y += acc[1]; v.z += acc[2]; v.w += acc[3];
        *(float4*)o = v;
    } else {
        __half* o = outB + (size_t)node * 64 + (lane - 16) * 4;
        __half2 hh[2];
        hh[0] = __floats2half2_rn(acc[0], acc[1]);
        hh[1] = __floats2half2_rn(acc[2], acc[3]);
        *(uint2*)o = *(uint2*)hh;
    }
}

__global__ __launch_bounds__(256)
void k_spmm2acc(const __half* __restrict__ src, float* __restrict__ out, int n)
{
    int node = blockIdx.x * 8 + (threadIdx.x >> 5);
    if (node >= n) return;
    int lane = threadIdx.x & 31;
    int s = g_colptr[node];
    int e = g_colptr[node + 1];
    float acc[2] = {0.f, 0.f};

    for (int p = s; p < e; p++) {
        int2  ed = g_edge[p];
        int   r = ed.x;
        float w = __int_as_float(ed.y);
        uint u = *(const uint*)(src + (size_t)r * 64 + lane * 2);
        float2 f = __half22float2(*(const __half2*)&u);
        acc[0] = fmaf(w, f.x, acc[0]);
        acc[1] = fmaf(w, f.y, acc[1]);
    }
    float* o = out + (size_t)node * 64 + lane * 2;
    float2 v = *(float2*)o;
    v.x += acc[0]; v.y += acc[1];
    *(float2*)o = v;
}

// ===================== BatchNorm stats (128-col slice) + finalize =====================
__global__ void k_bnstats(const __half* __restrict__ H, int N, int C, int colOff) {
    int col = colOff + threadIdx.x;
    int r0 = blockIdx.x * 256;
    int r1 = min(r0 + 256, N);
    float s = 0.f, s2 = 0.f;
    for (int r = r0; r < r1; r++) {
        float v = __half2float(H[(size_t)r * C + col]);
        s += v;
        s2 += v * v;
    }
    atomicAdd(&g_bnsum[col], s);
    atomicAdd(&g_bnsq[col],  s2);
}
__global__ void k_bnfin(const float* __restrict__ gma, const float* __restrict__ bet,
                        float invN) {
    int c = threadIdx.x;
    float mu  = g_bnsum[c] * invN;
    float var = g_bnsq[c] * invN - mu * mu;
    float sc  = gma[c] * rsqrtf(var + EPSV);
    g_bnsc[c] = sc;
    g_bnsh[c] = bet[c] - mu * sc;
}

extern "C" void kernel_launch(void* const* d_in, const int* in_sizes, int n_in,
                              void* d_out, int out_size) {
    const float* x    = (const float*)d_in[0];
    const void*  ei   = d_in[1];
    const float* W0   = (const float*)d_in[2];
    const float* b0   = (const float*)d_in[3];
    const float* W1   = (const float*)d_in[4];
    const float* b1   = (const float*)d_in[5];
    const float* W2   = (const float*)d_in[6];
    const float* b2   = (const float*)d_in[7];
    const float* bn0g = (const float*)d_in[8];
    const float* bn0b = (const float*)d_in[9];
    const float* bn1g = (const float*)d_in[10];
    const float* bn1b = (const float*)d_in[11];
    const float* fpW  = (const float*)d_in[12];
    const float* fpb  = (const float*)d_in[13];
    float*       out  = (float*)d_out;

    const int N = in_sizes[0] / 128;
    int E = in_sizes[1] / 2;
    if (E > EMAXC) E = in_sizes[1] / 4;

    int   *deg, *cursor;
    float *bnsum, *bnsq, *b2f;
    __half *tc, *t1h, *hA, *hB, *bhi, *blo;
    cudaGetSymbolAddress((void**)&deg,    g_deg);
    cudaGetSymbolAddress((void**)&cursor, g_cursor);
    cudaGetSymbolAddress((void**)&tc,     g_tc);
    cudaGetSymbolAddress((void**)&t1h,    g_t1h);
    cudaGetSymbolAddress((void**)&hA,     g_hA);
    cudaGetSymbolAddress((void**)&hB,     g_hB);
    cudaGetSymbolAddress((void**)&bnsum,  g_bnsum);
    cudaGetSymbolAddress((void**)&bnsq,   g_bnsq);
    cudaGetSymbolAddress((void**)&b2f,    g_b2f);
    cudaGetSymbolAddress((void**)&bhi,    g_Bhi);
    cudaGetSymbolAddress((void**)&blo,    g_Blo);

    const float invN = 1.f / (float)N;
    const int nblk = (N + 255) / 256;
    const int sb = (N + 7) / 8;

    const bool fork = g_si.ok;
    cudaStream_t sp = fork ? g_si.s1 : (cudaStream_t)0;
    auto forkTo = [&](cudaEvent_t ev) {
        if (fork) { cudaEventRecord(ev, 0); cudaStreamWaitEvent(sp, ev, 0); }
    };
    auto joinFrom = [&](cudaEvent_t ev) {
        if (fork) { cudaEventRecord(ev, sp); cudaStreamWaitEvent(0, ev, 0); }
    };

    // -------- main: minimal critical path to layer-0 GEMM --------
    k_cvtx<<<(N * 128 / 8 + 255) / 256, 256>>>(x, t1h, N * 128 / 8);
    k_prepB<<<(3 * 128 * 128 + 255) / 256, 256>>>(W0, 128, 128, 3, BOFF0);

    // -------- fork: preproc + remaining weight prep on side stream --------
    forkTo(g_si.ev[0]);
    k_detect<<<1, 256, 0, sp>>>((const int*)ei, in_sizes[1]);
    cudaMemsetAsync(deg,    0, (size_t)N * sizeof(int), sp);
    cudaMemsetAsync(cursor, 0, (size_t)N * sizeof(int), sp);
    k_deg<<<(E + 255) / 256, 256, 0, sp>>>(ei, E, N);
    k_blksum<<<nblk, 256, 0, sp>>>(N);
    k_scanblk<<<1, 512, 0, sp>>>(nblk);
    k_scanout<<<nblk, 256, 0, sp>>>(N);
    k_scatter<<<(E + 255) / 256, 256, 0, sp>>>(ei, E, N);
    k_prepB<<<(3 * 384 * 128 + 255) / 256, 256, 0, sp>>>(W1, 384, 128, 3, BOFF1);
    k_prepU<<<(3 * 384 * 64 + 255) / 256, 256, 0, sp>>>(W2, fpW);
    k_prepbf<<<1, 192, 0, sp>>>(b2, fpW, fpb);

    // -------- main: layer-0 GEMM (B hi-only; BN0 absorbs quantization) --------
    launch_hgemm<128, 384, 128, false, false, false>(t1h, bhi + BOFF0, blo + BOFF0, b0,
                                                     hA, 384, tc, 256, tc + 128, 256, N);
    cudaMemsetAsync(bnsum, 0, 384 * sizeof(float));
    cudaMemsetAsync(bnsq,  0, 384 * sizeof(float));

    // join preproc (spmm needs CSC); fork bnstats(hop0) to side
    joinFrom(g_si.ev[1]);
    forkTo(g_si.ev[2]);
    k_bnstats<<<nblk, 128, 0, sp>>>(hA, N, 384, 0);

    k_spmm1<256><<<sb, 256>>>(tc, hA + 128, 384, t1h, N);
    forkTo(g_si.ev[3]);
    k_bnstats<<<nblk, 128, 0, sp>>>(hA, N, 384, 128);
    k_spmm2<128><<<sb, 256>>>(t1h, hA + 256, 384, N);
    k_bnstats<<<nblk, 128>>>(hA, N, 384, 256);
    joinFrom(g_si.ev[4]);
    k_bnfin<<<1, 384>>>(bn0g, bn0b, invN);
    cudaMemsetAsync(bnsum, 0, 384 * sizeof(float));
    cudaMemsetAsync(bnsq,  0, 384 * sizeof(float));

    // -------- layer 1 (BN0+ReLU fused; B hi-only; BN1 absorbs quantization) --------
    launch_hgemm<384, 384, 128, true, false, false>(hA, bhi + BOFF1, blo + BOFF1, b1,
                                                    hB, 384, tc, 256, tc + 128, 256, N);
    forkTo(g_si.ev[5]);
    k_bnstats<<<nblk, 128, 0, sp>>>(hB, N, 384, 0);
    k_spmm1<256><<<sb, 256>>>(tc, hB + 128, 384, t1h, N);
    forkTo(g_si.ev[0]);
    k_bnstats<<<nblk, 128, 0, sp>>>(hB, N, 384, 128);
    k_spmm2<128><<<sb, 256>>>(t1h, hB + 256, 384, N);
    k_bnstats<<<nblk, 128>>>(hB, N, 384, 256);
    joinFrom(g_si.ev[1]);
    k_bnfin<<<1, 384>>>(bn1g, bn1b, invN);

    // -------- layer 2 fused with final projection (B hi-only) --------
    launch_hgemm<384, 192, 64, true, true, false>(hB, bhi + BOFF2, blo + BOFF2, b2f,
                                                  out, 64, tc, 128, tc + 64, 128, N);
    k_spmm1acc<<<sb, 256>>>(tc, out, t1h, N);
    k_spmm2acc<<<sb, 256>>>(t1h, out, N);
}